// round 4
// baseline (speedup 1.0000x reference)
#include <cuda_runtime.h>
#include <math.h>
#include <stdint.h>

namespace {

constexpr int kN = 128, kF = 16, kH = 256, kHeads = 4, kFF = 512,
              kOut = 64, kBF = 3, kL = 2, kP = 384, kT = 512, kE = 127,
              kDH = 64, kTN = kT * kN;

// ---- static device scratch (allocation-free) ----
__device__ float g_x[kTN * kH];          // 64 MB
__device__ float g_qkv[kTN * 3 * kH];    // 192 MB
__device__ float g_attn[kTN * kH];       // 64 MB
__device__ float g_ff[kTN * kFF];        // 128 MB
__device__ float g_y[kTN * kH];          // 64 MB
__device__ float g_outpre[kT * kOut];
__device__ float g_WposT[kP * kH];       // transposed W_pos, [P][H]
__device__ int g_parent[kTN];
__device__ int g_slot[kTN];
__device__ int g_maxno[kT];

// ---------------------------------------------------------------------------
// Tree prep
// ---------------------------------------------------------------------------
__global__ void init_parent_kernel() {
  int i = blockIdx.x * blockDim.x + threadIdx.x;
  if (i < kTN) g_parent[i] = -1;
}

__global__ void edges_kernel(const int* __restrict__ adj) {
  int i = blockIdx.x * blockDim.x + threadIdx.x;
  if (i >= kT * kE) return;
  int p = adj[3 * i], c = adj[3 * i + 1], s = adj[3 * i + 2];
  if (p >= 0 && c >= 0 && c < kTN) {
    g_parent[c] = p;
    g_slot[c] = s;
  }
}

__global__ void maxno_kernel(const int* __restrict__ no) {
  __shared__ int red[128];
  int t = blockIdx.x;
  red[threadIdx.x] = no[t * kN + threadIdx.x];
  __syncthreads();
  for (int s = 64; s > 0; s >>= 1) {
    if (threadIdx.x < s)
      red[threadIdx.x] = max(red[threadIdx.x], red[threadIdx.x + s]);
    __syncthreads();
  }
  if (threadIdx.x == 0) g_maxno[t] = red[0];
}

__global__ void transpose_wpos_kernel(const float* __restrict__ W_pos) {
  int i = blockIdx.x * blockDim.x + threadIdx.x;
  if (i >= kP * kH) return;
  int p = i / kH, h = i % kH;
  g_WposT[p * kH + h] = W_pos[h * kP + p];
}

// ---------------------------------------------------------------------------
// Embedding: 32 tokens per block, coalesced W_posT access.
// ---------------------------------------------------------------------------
__global__ void embed_kernel(const float* __restrict__ forest,
                             const int* __restrict__ no,
                             const float* __restrict__ W_in,
                             const float* __restrict__ b_in,
                             const float* __restrict__ b_pos) {
  __shared__ float Wins[kF][kH];
  __shared__ float bib[kH];
  __shared__ float fs[32][kF];
  __shared__ int anc[32][8];
  __shared__ int cnt[32];
  int tid = threadIdx.x;
  int base = blockIdx.x * 32;
#pragma unroll
  for (int j = 0; j < kH * kF / 256; ++j) {
    int idx = tid + j * 256;
    int h = idx / kF, f = idx % kF;
    Wins[f][h] = W_in[idx];
  }
  bib[tid] = b_in[tid] + b_pos[tid];
  {
    int idx = tid;
    if (idx < 32 * kF) {
      int tk = idx / kF, f = idx % kF;
      fs[tk][f] = forest[(size_t)(base + tk) * kF + f];
    }
    idx = tid + 256;
    if (idx < 32 * kF) {
      int tk = idx / kF, f = idx % kF;
      fs[tk][f] = forest[(size_t)(base + tk) * kF + f];
    }
  }
  if (tid < 32) {
    int tok = base + tid;
    int tree = tok / kN;
    int mx = g_maxno[tree];
    int c = tok, n = 0;
    for (int it = 0; it < 8; ++it) {
      int p = g_parent[c];
      if (p < 0) break;
      int pd = mx - no[p];
      int s = g_slot[c] + 1;
      s = s < 0 ? 0 : (s > kBF - 1 ? kBF - 1 : s);
      int idx = pd * kBF + s;
      if (idx >= 0 && idx < kP) anc[tid][n++] = idx;
      c = p;
    }
    cnt[tid] = n;
  }
  __syncthreads();
  int h = tid;
  for (int tk = 0; tk < 32; ++tk) {
    float acc = bib[h];
#pragma unroll
    for (int f = 0; f < kF; ++f) acc += fs[tk][f] * Wins[f][h];
    int c = cnt[tk];
    for (int a = 0; a < c; ++a) acc += g_WposT[anc[tk][a] * kH + h];
    g_x[(size_t)(base + tk) * kH + h] = acc;
  }
}

// ---------------------------------------------------------------------------
// tf32 mma helpers
// ---------------------------------------------------------------------------
enum { EPI_BIAS = 0, EPI_RELU = 1, EPI_RES = 2 };

__device__ __forceinline__ float to_tf32(float x) {
  uint32_t u;
  asm("cvt.rna.tf32.f32 %0, %1;" : "=r"(u) : "f"(x));
  return __uint_as_float(u);
}

__device__ __forceinline__ void mma_tf32(float* c, const uint32_t* a,
                                         const uint32_t* b) {
  asm("mma.sync.aligned.m16n8k8.row.col.f32.tf32.tf32.f32 "
      "{%0,%1,%2,%3},{%4,%5,%6,%7},{%8,%9},{%0,%1,%2,%3};"
      : "+f"(c[0]), "+f"(c[1]), "+f"(c[2]), "+f"(c[3])
      : "r"(a[0]), "r"(a[1]), "r"(a[2]), "r"(a[3]), "r"(b[0]), "r"(b[1]));
}

// ---------------------------------------------------------------------------
// tf32 tensor-core GEMM (unchanged from R2)
// ---------------------------------------------------------------------------
template <int EPI>
__global__ __launch_bounds__(256) void gemm_tc(const float* __restrict__ A,
                                               const float* __restrict__ W,
                                               const float* __restrict__ bias,
                                               const float* __restrict__ res,
                                               float* __restrict__ C, int M,
                                               int Nd, int K) {
  __shared__ float As[128][36];
  __shared__ float Bs[128][36];
  int tid = threadIdx.x;
  int lane = tid & 31, warp = tid >> 5;
  int g = lane >> 2, tg = lane & 3;
  int wm = (warp & 1) * 64;
  int wn = (warp >> 1) * 32;
  int m0 = blockIdx.y * 128, n0 = blockIdx.x * 128;

  int lr = tid >> 3;
  int lk = (tid & 7) * 4;

  float acc[4][4][4];
#pragma unroll
  for (int i = 0; i < 4; ++i)
#pragma unroll
    for (int j = 0; j < 4; ++j)
#pragma unroll
      for (int c = 0; c < 4; ++c) acc[i][j][c] = 0.f;

  const float* Ag = A + (size_t)(m0 + lr) * K + lk;
  const float* Wg = W + (size_t)(n0 + lr) * K + lk;

  float4 ra[4], rb[4];
#pragma unroll
  for (int p = 0; p < 4; ++p) {
    ra[p] = *(const float4*)(Ag + (size_t)(32 * p) * K);
    rb[p] = *(const float4*)(Wg + (size_t)(32 * p) * K);
  }

  for (int k0 = 0;;) {
#pragma unroll
    for (int p = 0; p < 4; ++p) {
      float* as = &As[lr + 32 * p][lk];
      as[0] = to_tf32(ra[p].x);
      as[1] = to_tf32(ra[p].y);
      as[2] = to_tf32(ra[p].z);
      as[3] = to_tf32(ra[p].w);
      float* bs = &Bs[lr + 32 * p][lk];
      bs[0] = to_tf32(rb[p].x);
      bs[1] = to_tf32(rb[p].y);
      bs[2] = to_tf32(rb[p].z);
      bs[3] = to_tf32(rb[p].w);
    }
    __syncthreads();
    k0 += 32;
    bool more = k0 < K;
    if (more) {
#pragma unroll
      for (int p = 0; p < 4; ++p) {
        ra[p] = *(const float4*)(Ag + (size_t)(32 * p) * K + k0);
        rb[p] = *(const float4*)(Wg + (size_t)(32 * p) * K + k0);
      }
    }
#pragma unroll
    for (int ks = 0; ks < 4; ++ks) {
      int kb = ks * 8;
      uint32_t af[4][4], bf[4][2];
#pragma unroll
      for (int mi = 0; mi < 4; ++mi) {
        int r = wm + mi * 16 + g;
        af[mi][0] = __float_as_uint(As[r][kb + tg]);
        af[mi][1] = __float_as_uint(As[r + 8][kb + tg]);
        af[mi][2] = __float_as_uint(As[r][kb + tg + 4]);
        af[mi][3] = __float_as_uint(As[r + 8][kb + tg + 4]);
      }
#pragma unroll
      for (int nj = 0; nj < 4; ++nj) {
        int c = wn + nj * 8 + g;
        bf[nj][0] = __float_as_uint(Bs[c][kb + tg]);
        bf[nj][1] = __float_as_uint(Bs[c][kb + tg + 4]);
      }
#pragma unroll
      for (int mi = 0; mi < 4; ++mi)
#pragma unroll
        for (int nj = 0; nj < 4; ++nj) mma_tf32(acc[mi][nj], af[mi], bf[nj]);
    }
    if (!more) break;
    __syncthreads();
  }

#pragma unroll
  for (int nj = 0; nj < 4; ++nj) {
    int col = n0 + wn + nj * 8 + tg * 2;
    float b0 = bias[col], b1 = bias[col + 1];
#pragma unroll
    for (int mi = 0; mi < 4; ++mi) {
      int row = m0 + wm + mi * 16 + g;
      float v00 = acc[mi][nj][0] + b0;
      float v01 = acc[mi][nj][1] + b1;
      float v10 = acc[mi][nj][2] + b0;
      float v11 = acc[mi][nj][3] + b1;
      if (EPI == EPI_RELU) {
        v00 = fmaxf(v00, 0.f);
        v01 = fmaxf(v01, 0.f);
        v10 = fmaxf(v10, 0.f);
        v11 = fmaxf(v11, 0.f);
      }
      if (EPI == EPI_RES) {
        float2 r0 = *(const float2*)(res + (size_t)row * Nd + col);
        float2 r1 = *(const float2*)(res + (size_t)(row + 8) * Nd + col);
        v00 += r0.x;
        v01 += r0.y;
        v10 += r1.x;
        v11 += r1.y;
      }
      float2 o0 = {v00, v01}, o1 = {v10, v11};
      *(float2*)(C + (size_t)row * Nd + col) = o0;
      *(float2*)(C + (size_t)(row + 8) * Nd + col) = o1;
    }
  }
}

// ---------------------------------------------------------------------------
// Tensor-core attention: one block per (tree, head), 8 warps.
// S = Q@K^T via mma (K=64), warp-parallel softmax, O = P@V via mma (K=128).
// Dynamic smem: Qs[128][68] | KVs(K[128][68] then V^T[64][132]) | Ss[128][132]
// ---------------------------------------------------------------------------
constexpr int kQS = 68;    // Q/K smem stride (4 mod 32 -> conflict-free frags)
constexpr int kSS = 132;   // S / V^T stride
constexpr int kAttnSmem = (2 * 128 * kQS + 128 * kSS) * 4;  // 137216 B

__global__ __launch_bounds__(256) void attn_tc_kernel(
    const float* __restrict__ qkv, float* __restrict__ out) {
  extern __shared__ float sm[];
  float* Qs = sm;
  float* KVs = sm + 128 * kQS;
  float* Ss = sm + 2 * 128 * kQS;
  int t = blockIdx.x >> 2, h = blockIdx.x & 3;
  int tid = threadIdx.x, lane = tid & 31, warp = tid >> 5;
  int g = lane >> 2, tg = lane & 3;
  const size_t base = (size_t)t * kN * (3 * kH);

  // load Q, K (tf32) — 2 threads per row, 32 cols each
  int row = tid >> 1, part = tid & 1;
  {
    const float* qp = qkv + base + (size_t)row * (3 * kH) + h * kDH + part * 32;
    const float* kp = qp + kH;
    float* qd = Qs + row * kQS + part * 32;
    float* kd = KVs + row * kQS + part * 32;
#pragma unroll
    for (int i = 0; i < 8; ++i) {
      float4 v = *(const float4*)(qp + i * 4);
      qd[i * 4 + 0] = to_tf32(v.x);
      qd[i * 4 + 1] = to_tf32(v.y);
      qd[i * 4 + 2] = to_tf32(v.z);
      qd[i * 4 + 3] = to_tf32(v.w);
      float4 w = *(const float4*)(kp + i * 4);
      kd[i * 4 + 0] = to_tf32(w.x);
      kd[i * 4 + 1] = to_tf32(w.y);
      kd[i * 4 + 2] = to_tf32(w.z);
      kd[i * 4 + 3] = to_tf32(w.w);
    }
  }
  __syncthreads();

  // mma1: S[128,128] = Q @ K^T, K-dim 64
  int wm = (warp & 1) * 64;
  int wn = (warp >> 1) * 32;
  {
    float acc[4][4][4];
#pragma unroll
    for (int i = 0; i < 4; ++i)
#pragma unroll
      for (int j = 0; j < 4; ++j)
#pragma unroll
        for (int c = 0; c < 4; ++c) acc[i][j][c] = 0.f;
#pragma unroll
    for (int ks = 0; ks < 8; ++ks) {
      int kb = ks * 8;
      uint32_t af[4][4], bf[4][2];
#pragma unroll
      for (int mi = 0; mi < 4; ++mi) {
        const float* r0 = Qs + (wm + mi * 16 + g) * kQS + kb;
        af[mi][0] = __float_as_uint(r0[tg]);
        af[mi][1] = __float_as_uint(r0[8 * kQS + tg]);
        af[mi][2] = __float_as_uint(r0[tg + 4]);
        af[mi][3] = __float_as_uint(r0[8 * kQS + tg + 4]);
      }
#pragma unroll
      for (int nj = 0; nj < 4; ++nj) {
        const float* c0 = KVs + (wn + nj * 8 + g) * kQS + kb;
        bf[nj][0] = __float_as_uint(c0[tg]);
        bf[nj][1] = __float_as_uint(c0[tg + 4]);
      }
#pragma unroll
      for (int mi = 0; mi < 4; ++mi)
#pragma unroll
        for (int nj = 0; nj < 4; ++nj) mma_tf32(acc[mi][nj], af[mi], bf[nj]);
    }
    const float scale = 0.125f;
#pragma unroll
    for (int mi = 0; mi < 4; ++mi)
#pragma unroll
      for (int nj = 0; nj < 4; ++nj) {
        int r0 = wm + mi * 16 + g;
        int col = wn + nj * 8 + tg * 2;
        Ss[r0 * kSS + col] = acc[mi][nj][0] * scale;
        Ss[r0 * kSS + col + 1] = acc[mi][nj][1] * scale;
        Ss[(r0 + 8) * kSS + col] = acc[mi][nj][2] * scale;
        Ss[(r0 + 8) * kSS + col + 1] = acc[mi][nj][3] * scale;
      }
  }
  __syncthreads();  // S complete; all mma1 reads of KVs done

  // V^T into KVs: Vt[d][j] = V[j][d]
  {
    const float* vp =
        qkv + base + (size_t)row * (3 * kH) + 2 * kH + h * kDH + part * 32;
#pragma unroll
    for (int i = 0; i < 8; ++i) {
      float4 v = *(const float4*)(vp + i * 4);
      int d = part * 32 + i * 4;
      KVs[(d + 0) * kSS + row] = to_tf32(v.x);
      KVs[(d + 1) * kSS + row] = to_tf32(v.y);
      KVs[(d + 2) * kSS + row] = to_tf32(v.z);
      KVs[(d + 3) * kSS + row] = to_tf32(v.w);
    }
  }

  // softmax: warp w owns rows w*16..w*16+15
#pragma unroll 1
  for (int i = 0; i < 16; ++i) {
    float* srow = Ss + (warp * 16 + i) * kSS;
    float v0 = srow[lane], v1 = srow[lane + 32], v2 = srow[lane + 64],
          v3 = srow[lane + 96];
    float mx = fmaxf(fmaxf(v0, v1), fmaxf(v2, v3));
#pragma unroll
    for (int s = 16; s; s >>= 1) mx = fmaxf(mx, __shfl_xor_sync(~0u, mx, s));
    float e0 = __expf(v0 - mx), e1 = __expf(v1 - mx), e2 = __expf(v2 - mx),
          e3 = __expf(v3 - mx);
    float sum = e0 + e1 + e2 + e3;
#pragma unroll
    for (int s = 16; s; s >>= 1) sum += __shfl_xor_sync(~0u, sum, s);
    float inv = 1.f / sum;
    srow[lane] = to_tf32(e0 * inv);
    srow[lane + 32] = to_tf32(e1 * inv);
    srow[lane + 64] = to_tf32(e2 * inv);
    srow[lane + 96] = to_tf32(e3 * inv);
  }
  __syncthreads();  // P and V^T ready

  // mma2: O[128,64] = P @ V, K-dim 128
  int wn2 = (warp >> 1) * 16;
  {
    float acc[4][2][4];
#pragma unroll
    for (int i = 0; i < 4; ++i)
#pragma unroll
      for (int j = 0; j < 2; ++j)
#pragma unroll
        for (int c = 0; c < 4; ++c) acc[i][j][c] = 0.f;
#pragma unroll
    for (int ks = 0; ks < 16; ++ks) {
      int kb = ks * 8;
      uint32_t af[4][4], bf[2][2];
#pragma unroll
      for (int mi = 0; mi < 4; ++mi) {
        const float* r0 = Ss + (wm + mi * 16 + g) * kSS + kb;
        af[mi][0] = __float_as_uint(r0[tg]);
        af[mi][1] = __float_as_uint(r0[8 * kSS + tg]);
        af[mi][2] = __float_as_uint(r0[tg + 4]);
        af[mi][3] = __float_as_uint(r0[8 * kSS + tg + 4]);
      }
#pragma unroll
      for (int nj = 0; nj < 2; ++nj) {
        const float* c0 = KVs + (wn2 + nj * 8 + g) * kSS + kb;
        bf[nj][0] = __float_as_uint(c0[tg]);
        bf[nj][1] = __float_as_uint(c0[tg + 4]);
      }
#pragma unroll
      for (int mi = 0; mi < 4; ++mi)
#pragma unroll
        for (int nj = 0; nj < 2; ++nj) mma_tf32(acc[mi][nj], af[mi], bf[nj]);
    }
    float* op = out + (size_t)(t * kN) * kH + h * kDH;
#pragma unroll
    for (int mi = 0; mi < 4; ++mi)
#pragma unroll
      for (int nj = 0; nj < 2; ++nj) {
        int r0 = wm + mi * 16 + g;
        int col = wn2 + nj * 8 + tg * 2;
        float2 o0 = {acc[mi][nj][0], acc[mi][nj][1]};
        float2 o1 = {acc[mi][nj][2], acc[mi][nj][3]};
        *(float2*)(op + (size_t)r0 * kH + col) = o0;
        *(float2*)(op + (size_t)(r0 + 8) * kH + col) = o1;
      }
  }
}

// ---------------------------------------------------------------------------
// LayerNorm: warp per token, 8 tokens per block, shuffle reductions.
// ---------------------------------------------------------------------------
__global__ __launch_bounds__(256) void ln_kernel(const float* __restrict__ y,
                                                 const float* __restrict__ w,
                                                 const float* __restrict__ b,
                                                 float* __restrict__ x) {
  int warp = threadIdx.x >> 5, lane = threadIdx.x & 31;
  size_t tok = (size_t)blockIdx.x * 8 + warp;
  const float* yp = y + tok * kH;
  float4 a = *(const float4*)(yp + lane * 4);
  float4 c = *(const float4*)(yp + 128 + lane * 4);
  float sum = a.x + a.y + a.z + a.w + c.x + c.y + c.z + c.w;
#pragma unroll
  for (int s = 16; s; s >>= 1) sum += __shfl_xor_sync(~0u, sum, s);
  float mu = sum * (1.f / kH);
  float d0 = a.x - mu, d1 = a.y - mu, d2 = a.z - mu, d3 = a.w - mu;
  float d4 = c.x - mu, d5 = c.y - mu, d6 = c.z - mu, d7 = c.w - mu;
  float sq = d0 * d0 + d1 * d1 + d2 * d2 + d3 * d3 + d4 * d4 + d5 * d5 +
             d6 * d6 + d7 * d7;
#pragma unroll
  for (int s = 16; s; s >>= 1) sq += __shfl_xor_sync(~0u, sq, s);
  float inv = rsqrtf(sq * (1.f / kH) + 1e-5f);
  float4 w0 = *(const float4*)(w + lane * 4);
  float4 w1 = *(const float4*)(w + 128 + lane * 4);
  float4 b0 = *(const float4*)(b + lane * 4);
  float4 b1 = *(const float4*)(b + 128 + lane * 4);
  float* xp = x + tok * kH;
  float4 o0 = {d0 * inv * w0.x + b0.x, d1 * inv * w0.y + b0.y,
               d2 * inv * w0.z + b0.z, d3 * inv * w0.w + b0.w};
  float4 o1 = {d4 * inv * w1.x + b1.x, d5 * inv * w1.y + b1.y,
               d6 * inv * w1.z + b1.z, d7 * inv * w1.w + b1.w};
  *(float4*)(xp + lane * 4) = o0;
  *(float4*)(xp + 128 + lane * 4) = o1;
}

// ---------------------------------------------------------------------------
// Output GEMM: out_pre[512,64] = x[512, 32768] @ W_out[64,32768]^T, split-K
// ---------------------------------------------------------------------------
constexpr int kKTotal = kN * kH;
constexpr int kKSplit = 16;
constexpr int kKChunk = kKTotal / kKSplit;

__global__ void zero_outpre() {
  int i = blockIdx.x * blockDim.x + threadIdx.x;
  if (i < kT * kOut) g_outpre[i] = 0.f;
}

__global__ void gemm_out_kernel(const float* __restrict__ Afull,
                                const float* __restrict__ Wout) {
  __shared__ float As[16][68];
  __shared__ float Bs[16][68];
  int m0 = blockIdx.y * 64;
  int kc0 = blockIdx.x * kKChunk;
  int tid = threadIdx.x;
  int tx = tid & 15, ty = tid >> 4;
  int lm = tid >> 2, lk = (tid & 3) * 4;
  float acc[4][4] = {};
  const float* Aptr = Afull + (size_t)(m0 + lm) * kKTotal + kc0 + lk;
  const float* Wptr = Wout + (size_t)lm * kKTotal + kc0 + lk;
  for (int k0 = 0; k0 < kKChunk; k0 += 16) {
    float4 av = *(const float4*)(Aptr + k0);
    float4 wv = *(const float4*)(Wptr + k0);
    As[lk + 0][lm] = av.x;
    As[lk + 1][lm] = av.y;
    As[lk + 2][lm] = av.z;
    As[lk + 3][lm] = av.w;
    Bs[lk + 0][lm] = wv.x;
    Bs[lk + 1][lm] = wv.y;
    Bs[lk + 2][lm] = wv.z;
    Bs[lk + 3][lm] = wv.w;
    __syncthreads();
#pragma unroll
    for (int k = 0; k < 16; ++k) {
      float4 a4 = *(const float4*)&As[k][ty * 4];
      float4 b4 = *(const float4*)&Bs[k][tx * 4];
      float a[4] = {a4.x, a4.y, a4.z, a4.w};
      float b[4] = {b4.x, b4.y, b4.z, b4.w};
#pragma unroll
      for (int i = 0; i < 4; ++i)
#pragma unroll
        for (int j = 0; j < 4; ++j) acc[i][j] += a[i] * b[j];
    }
    __syncthreads();
  }
#pragma unroll
  for (int i = 0; i < 4; ++i)
#pragma unroll
    for (int j = 0; j < 4; ++j)
      atomicAdd(&g_outpre[(m0 + ty * 4 + i) * kOut + tx * 4 + j], acc[i][j]);
}

__global__ void lnf_kernel(const float* __restrict__ b_out,
                           const float* __restrict__ w,
                           const float* __restrict__ bb,
                           float* __restrict__ out) {
  __shared__ float red[64];
  int t = blockIdx.x, o = threadIdx.x;
  float v = g_outpre[t * kOut + o] + b_out[o];
  red[o] = v;
  __syncthreads();
  for (int s = 32; s > 0; s >>= 1) {
    if (o < s) red[o] += red[o + s];
    __syncthreads();
  }
  float mu = red[0] * (1.f / kOut);
  __syncthreads();
  float d = v - mu;
  red[o] = d * d;
  __syncthreads();
  for (int s = 32; s > 0; s >>= 1) {
    if (o < s) red[o] += red[o + s];
    __syncthreads();
  }
  float var = red[0] * (1.f / kOut);
  out[t * kOut + o] = d * rsqrtf(var + 1e-5f) * w[o] + bb[o];
}

}  // namespace

extern "C" void kernel_launch(void* const* d_in, const int* in_sizes, int n_in,
                              void* d_out, int out_size) {
  const float* forest = (const float*)d_in[0];
  const int* adj = (const int*)d_in[1];
  const int* no = (const int*)d_in[2];
  const float* W_in = (const float*)d_in[3];
  const float* b_in = (const float*)d_in[4];
  const float* W_pos = (const float*)d_in[5];
  const float* b_pos = (const float*)d_in[6];
  const float* qkv_w = (const float*)d_in[7];
  const float* qkv_b = (const float*)d_in[8];
  const float* outp_w = (const float*)d_in[9];
  const float* outp_b = (const float*)d_in[10];
  const float* ln1_w = (const float*)d_in[11];
  const float* ln1_b = (const float*)d_in[12];
  const float* ff1_w = (const float*)d_in[13];
  const float* ff1_b = (const float*)d_in[14];
  const float* ff2_w = (const float*)d_in[15];
  const float* ff2_b = (const float*)d_in[16];
  const float* ln2_w = (const float*)d_in[17];
  const float* ln2_b = (const float*)d_in[18];
  const float* W_out = (const float*)d_in[19];
  const float* b_out = (const float*)d_in[20];
  const float* lnf_w = (const float*)d_in[21];
  const float* lnf_b = (const float*)d_in[22];
  float* out = (float*)d_out;

  float *px, *pqkv, *pattn, *pff, *py;
  cudaGetSymbolAddress((void**)&px, g_x);
  cudaGetSymbolAddress((void**)&pqkv, g_qkv);
  cudaGetSymbolAddress((void**)&pattn, g_attn);
  cudaGetSymbolAddress((void**)&pff, g_ff);
  cudaGetSymbolAddress((void**)&py, g_y);

  static bool attn_attr_set = false;
  if (!attn_attr_set) {
    cudaFuncSetAttribute(attn_tc_kernel,
                         cudaFuncAttributeMaxDynamicSharedMemorySize,
                         kAttnSmem);
    attn_attr_set = true;
  }

  init_parent_kernel<<<(kTN + 255) / 256, 256>>>();
  edges_kernel<<<(kT * kE + 255) / 256, 256>>>(adj);
  maxno_kernel<<<kT, 128>>>(no);
  transpose_wpos_kernel<<<(kP * kH + 255) / 256, 256>>>(W_pos);
  embed_kernel<<<kTN / 32, 256>>>(forest, no, W_in, b_in, b_pos);

  dim3 blk(256);
  for (int l = 0; l < kL; ++l) {
    gemm_tc<EPI_BIAS><<<dim3((3 * kH) / 128, kTN / 128), blk>>>(
        px, qkv_w + (size_t)l * 3 * kH * kH, qkv_b + (size_t)l * 3 * kH,
        nullptr, pqkv, kTN, 3 * kH, kH);
    attn_tc_kernel<<<kT * kHeads, 256, kAttnSmem>>>(pqkv, pattn);
    gemm_tc<EPI_RES><<<dim3(kH / 128, kTN / 128), blk>>>(
        pattn, outp_w + (size_t)l * kH * kH, outp_b + (size_t)l * kH, px, py,
        kTN, kH, kH);
    ln_kernel<<<kTN / 8, 256>>>(py, ln1_w + (size_t)l * kH,
                                ln1_b + (size_t)l * kH, px);
    gemm_tc<EPI_RELU><<<dim3(kFF / 128, kTN / 128), blk>>>(
        px, ff1_w + (size_t)l * kFF * kH, ff1_b + (size_t)l * kFF, nullptr,
        pff, kTN, kFF, kH);
    gemm_tc<EPI_RES><<<dim3(kH / 128, kTN / 128), blk>>>(
        pff, ff2_w + (size_t)l * kH * kFF, ff2_b + (size_t)l * kH, px, py, kTN,
        kH, kFF);
    ln_kernel<<<kTN / 8, 256>>>(py, ln2_w + (size_t)l * kH,
                                ln2_b + (size_t)l * kH, px);
  }

  zero_outpre<<<(kT * kOut + 255) / 256, 256>>>();
  gemm_out_kernel<<<dim3(kKSplit, kT / 64), blk>>>(px, W_out);
  lnf_kernel<<<kT, kOut>>>(b_out, lnf_w, lnf_b, out);
}

// round 6
// speedup vs baseline: 1.2471x; 1.2471x over previous
#include <cuda_runtime.h>
#include <math.h>
#include <stdint.h>

namespace {

constexpr int kN = 128, kF = 16, kH = 256, kHeads = 4, kFF = 512,
              kOut = 64, kBF = 3, kL = 2, kP = 384, kT = 512, kE = 127,
              kDH = 64, kTN = kT * kN;

// ---- static device scratch (allocation-free) ----
__device__ float g_x[kTN * kH];          // 64 MB
__device__ float g_qkv[kTN * 3 * kH];    // 192 MB
__device__ float g_attn[kTN * kH];       // 64 MB
__device__ float g_ff[kTN * kFF];        // 128 MB
__device__ float g_y[kTN * kH];          // 64 MB
__device__ float g_outpre[kT * kOut];
__device__ float g_WposT[kP * kH];       // transposed W_pos, [P][H]
__device__ int g_parent[kTN];
__device__ int g_slot[kTN];
__device__ int g_maxno[kT];

// ---------------------------------------------------------------------------
// Prep 1: parent/slot for every node (fused init+edges; node i's edge is
// adj[tree*kE + local-1] for local>=1, roots get -1).
// ---------------------------------------------------------------------------
__global__ void prep_parent_kernel(const int* __restrict__ adj) {
  int i = blockIdx.x * blockDim.x + threadIdx.x;
  if (i >= kTN) return;
  int local = i & (kN - 1);
  int tree = i >> 7;
  int par = -1, sl = 0;
  if (local != 0) {
    int e = tree * kE + local - 1;
    int p = adj[3 * e], c = adj[3 * e + 1], s = adj[3 * e + 2];
    if (c == i && p >= 0) {
      par = p;
      sl = s;
    }
  }
  g_parent[i] = par;
  g_slot[i] = sl;
}

// ---------------------------------------------------------------------------
// Prep 2: fused per-tree max(node_order) + W_pos transpose.
// Blocks [0,kT): maxno. Blocks [kT, kT+384): transpose.
// ---------------------------------------------------------------------------
__global__ void prep2_kernel(const int* __restrict__ no,
                             const float* __restrict__ W_pos) {
  if (blockIdx.x < kT) {
    __shared__ int red[128];
    int t = blockIdx.x;
    if (threadIdx.x < 128) red[threadIdx.x] = no[t * kN + threadIdx.x];
    __syncthreads();
    for (int s = 64; s > 0; s >>= 1) {
      if (threadIdx.x < s)
        red[threadIdx.x] = max(red[threadIdx.x], red[threadIdx.x + s]);
      __syncthreads();
    }
    if (threadIdx.x == 0) g_maxno[t] = red[0];
  } else {
    int i = (blockIdx.x - kT) * blockDim.x + threadIdx.x;
    if (i < kP * kH) {
      int p = i / kH, h = i % kH;
      g_WposT[p * kH + h] = W_pos[h * kP + p];
    }
  }
}

// ---------------------------------------------------------------------------
// Embedding: 32 tokens per block, coalesced W_posT access.
// ---------------------------------------------------------------------------
__global__ void embed_kernel(const float* __restrict__ forest,
                             const int* __restrict__ no,
                             const float* __restrict__ W_in,
                             const float* __restrict__ b_in,
                             const float* __restrict__ b_pos) {
  __shared__ float Wins[kF][kH];
  __shared__ float bib[kH];
  __shared__ float fs[32][kF];
  __shared__ int anc[32][8];
  __shared__ int cnt[32];
  int tid = threadIdx.x;
  int base = blockIdx.x * 32;
#pragma unroll
  for (int j = 0; j < kH * kF / 256; ++j) {
    int idx = tid + j * 256;
    int h = idx / kF, f = idx % kF;
    Wins[f][h] = W_in[idx];
  }
  bib[tid] = b_in[tid] + b_pos[tid];
  {
    int idx = tid;
    if (idx < 32 * kF) {
      int tk = idx / kF, f = idx % kF;
      fs[tk][f] = forest[(size_t)(base + tk) * kF + f];
    }
    idx = tid + 256;
    if (idx < 32 * kF) {
      int tk = idx / kF, f = idx % kF;
      fs[tk][f] = forest[(size_t)(base + tk) * kF + f];
    }
  }
  if (tid < 32) {
    int tok = base + tid;
    int tree = tok / kN;
    int mx = g_maxno[tree];
    int c = tok, n = 0;
    for (int it = 0; it < 8; ++it) {
      int p = g_parent[c];
      if (p < 0) break;
      int pd = mx - no[p];
      int s = g_slot[c] + 1;
      s = s < 0 ? 0 : (s > kBF - 1 ? kBF - 1 : s);
      int idx = pd * kBF + s;
      if (idx >= 0 && idx < kP) anc[tid][n++] = idx;
      c = p;
    }
    cnt[tid] = n;
  }
  __syncthreads();
  int h = tid;
  for (int tk = 0; tk < 32; ++tk) {
    float acc = bib[h];
#pragma unroll
    for (int f = 0; f < kF; ++f) acc += fs[tk][f] * Wins[f][h];
    int c = cnt[tk];
    for (int a = 0; a < c; ++a) acc += g_WposT[anc[tk][a] * kH + h];
    g_x[(size_t)(base + tk) * kH + h] = acc;
  }
}

// ---------------------------------------------------------------------------
// tf32 mma helpers
// ---------------------------------------------------------------------------
enum { EPI_BIAS = 0, EPI_RELU = 1, EPI_RES = 2 };

__device__ __forceinline__ float to_tf32(float x) {
  uint32_t u;
  asm("cvt.rna.tf32.f32 %0, %1;" : "=r"(u) : "f"(x));
  return __uint_as_float(u);
}

__device__ __forceinline__ void mma_tf32(float* c, const uint32_t* a,
                                         const uint32_t* b) {
  asm("mma.sync.aligned.m16n8k8.row.col.f32.tf32.tf32.f32 "
      "{%0,%1,%2,%3},{%4,%5,%6,%7},{%8,%9},{%0,%1,%2,%3};"
      : "+f"(c[0]), "+f"(c[1]), "+f"(c[2]), "+f"(c[3])
      : "r"(a[0]), "r"(a[1]), "r"(a[2]), "r"(a[3]), "r"(b[0]), "r"(b[1]));
}

// ---------------------------------------------------------------------------
// tf32 tensor-core GEMM: C[M,Nd] = A[M,K] @ W[Nd,K]^T + bias (+relu|+res)
// ---------------------------------------------------------------------------
template <int EPI>
__global__ __launch_bounds__(256) void gemm_tc(const float* __restrict__ A,
                                               const float* __restrict__ W,
                                               const float* __restrict__ bias,
                                               const float* __restrict__ res,
                                               float* __restrict__ C, int M,
                                               int Nd, int K) {
  __shared__ float As[128][36];
  __shared__ float Bs[128][36];
  int tid = threadIdx.x;
  int lane = tid & 31, warp = tid >> 5;
  int g = lane >> 2, tg = lane & 3;
  int wm = (warp & 1) * 64;
  int wn = (warp >> 1) * 32;
  int m0 = blockIdx.y * 128, n0 = blockIdx.x * 128;

  int lr = tid >> 3;
  int lk = (tid & 7) * 4;

  float acc[4][4][4];
#pragma unroll
  for (int i = 0; i < 4; ++i)
#pragma unroll
    for (int j = 0; j < 4; ++j)
#pragma unroll
      for (int c = 0; c < 4; ++c) acc[i][j][c] = 0.f;

  const float* Ag = A + (size_t)(m0 + lr) * K + lk;
  const float* Wg = W + (size_t)(n0 + lr) * K + lk;

  float4 ra[4], rb[4];
#pragma unroll
  for (int p = 0; p < 4; ++p) {
    ra[p] = *(const float4*)(Ag + (size_t)(32 * p) * K);
    rb[p] = *(const float4*)(Wg + (size_t)(32 * p) * K);
  }

  for (int k0 = 0;;) {
#pragma unroll
    for (int p = 0; p < 4; ++p) {
      float* as = &As[lr + 32 * p][lk];
      as[0] = to_tf32(ra[p].x);
      as[1] = to_tf32(ra[p].y);
      as[2] = to_tf32(ra[p].z);
      as[3] = to_tf32(ra[p].w);
      float* bs = &Bs[lr + 32 * p][lk];
      bs[0] = to_tf32(rb[p].x);
      bs[1] = to_tf32(rb[p].y);
      bs[2] = to_tf32(rb[p].z);
      bs[3] = to_tf32(rb[p].w);
    }
    __syncthreads();
    k0 += 32;
    bool more = k0 < K;
    if (more) {
#pragma unroll
      for (int p = 0; p < 4; ++p) {
        ra[p] = *(const float4*)(Ag + (size_t)(32 * p) * K + k0);
        rb[p] = *(const float4*)(Wg + (size_t)(32 * p) * K + k0);
      }
    }
#pragma unroll
    for (int ks = 0; ks < 4; ++ks) {
      int kb = ks * 8;
      uint32_t af[4][4], bf[4][2];
#pragma unroll
      for (int mi = 0; mi < 4; ++mi) {
        int r = wm + mi * 16 + g;
        af[mi][0] = __float_as_uint(As[r][kb + tg]);
        af[mi][1] = __float_as_uint(As[r + 8][kb + tg]);
        af[mi][2] = __float_as_uint(As[r][kb + tg + 4]);
        af[mi][3] = __float_as_uint(As[r + 8][kb + tg + 4]);
      }
#pragma unroll
      for (int nj = 0; nj < 4; ++nj) {
        int c = wn + nj * 8 + g;
        bf[nj][0] = __float_as_uint(Bs[c][kb + tg]);
        bf[nj][1] = __float_as_uint(Bs[c][kb + tg + 4]);
      }
#pragma unroll
      for (int mi = 0; mi < 4; ++mi)
#pragma unroll
        for (int nj = 0; nj < 4; ++nj) mma_tf32(acc[mi][nj], af[mi], bf[nj]);
    }
    if (!more) break;
    __syncthreads();
  }

#pragma unroll
  for (int nj = 0; nj < 4; ++nj) {
    int col = n0 + wn + nj * 8 + tg * 2;
    float b0 = bias[col], b1 = bias[col + 1];
#pragma unroll
    for (int mi = 0; mi < 4; ++mi) {
      int row = m0 + wm + mi * 16 + g;
      float v00 = acc[mi][nj][0] + b0;
      float v01 = acc[mi][nj][1] + b1;
      float v10 = acc[mi][nj][2] + b0;
      float v11 = acc[mi][nj][3] + b1;
      if (EPI == EPI_RELU) {
        v00 = fmaxf(v00, 0.f);
        v01 = fmaxf(v01, 0.f);
        v10 = fmaxf(v10, 0.f);
        v11 = fmaxf(v11, 0.f);
      }
      if (EPI == EPI_RES) {
        float2 r0 = *(const float2*)(res + (size_t)row * Nd + col);
        float2 r1 = *(const float2*)(res + (size_t)(row + 8) * Nd + col);
        v00 += r0.x;
        v01 += r0.y;
        v10 += r1.x;
        v11 += r1.y;
      }
      float2 o0 = {v00, v01}, o1 = {v10, v11};
      *(float2*)(C + (size_t)row * Nd + col) = o0;
      *(float2*)(C + (size_t)(row + 8) * Nd + col) = o1;
    }
  }
}

// ---------------------------------------------------------------------------
// Attention (scalar, R2 version): block per (tree, head), thread per query,
// online softmax with skip-rescale fast path.
// ---------------------------------------------------------------------------
__global__ void attn_kernel(const float* __restrict__ qkv,
                            float* __restrict__ out) {
  int t = blockIdx.x >> 2;
  int h = blockIdx.x & 3;
  int qi = threadIdx.x;
  __shared__ float Ks[64][64];
  __shared__ float Vs[64][64];
  const size_t base = (size_t)t * kN * (3 * kH);
  const float* qrow = qkv + base + (size_t)qi * (3 * kH) + h * kDH;
  float q[64];
#pragma unroll
  for (int d4 = 0; d4 < 16; ++d4) {
    float4 v = *(const float4*)(qrow + d4 * 4);
    q[d4 * 4 + 0] = v.x;
    q[d4 * 4 + 1] = v.y;
    q[d4 * 4 + 2] = v.z;
    q[d4 * 4 + 3] = v.w;
  }
  float m = -1e30f, l = 0.f;
  float o[64];
#pragma unroll
  for (int d = 0; d < 64; ++d) o[d] = 0.f;
  const float scale = 0.125f;
  for (int kt = 0; kt < 2; ++kt) {
    for (int idx = threadIdx.x; idx < 64 * 16; idx += 128) {
      int r = idx >> 4, d4 = idx & 15;
      const float* kp =
          qkv + base + (size_t)(kt * 64 + r) * (3 * kH) + kH + h * kDH + d4 * 4;
      const float* vp = qkv + base + (size_t)(kt * 64 + r) * (3 * kH) +
                        2 * kH + h * kDH + d4 * 4;
      *(float4*)&Ks[r][d4 * 4] = *(const float4*)kp;
      *(float4*)&Vs[r][d4 * 4] = *(const float4*)vp;
    }
    __syncthreads();
    for (int j = 0; j < 64; ++j) {
      float s = 0.f;
#pragma unroll
      for (int d = 0; d < 64; ++d) s += q[d] * Ks[j][d];
      s *= scale;
      if (s <= m) {
        float p = __expf(s - m);
        l += p;
#pragma unroll
        for (int d = 0; d < 64; ++d) o[d] += p * Vs[j][d];
      } else {
        float corr = __expf(m - s);
        l = l * corr + 1.f;
#pragma unroll
        for (int d = 0; d < 64; ++d) o[d] = o[d] * corr + Vs[j][d];
        m = s;
      }
    }
    __syncthreads();
  }
  float inv = 1.f / l;
  float* op = out + (size_t)(t * kN + qi) * kH + h * kDH;
#pragma unroll
  for (int d4 = 0; d4 < 16; ++d4) {
    float4 v;
    v.x = o[d4 * 4 + 0] * inv;
    v.y = o[d4 * 4 + 1] * inv;
    v.z = o[d4 * 4 + 2] * inv;
    v.w = o[d4 * 4 + 3] * inv;
    *(float4*)(op + d4 * 4) = v;
  }
}

// ---------------------------------------------------------------------------
// LayerNorm: warp per token, 8 tokens per block, shuffle reductions.
// ---------------------------------------------------------------------------
__global__ __launch_bounds__(256) void ln_kernel(const float* __restrict__ y,
                                                 const float* __restrict__ w,
                                                 const float* __restrict__ b,
                                                 float* __restrict__ x) {
  int warp = threadIdx.x >> 5, lane = threadIdx.x & 31;
  size_t tok = (size_t)blockIdx.x * 8 + warp;
  const float* yp = y + tok * kH;
  float4 a = *(const float4*)(yp + lane * 4);
  float4 c = *(const float4*)(yp + 128 + lane * 4);
  float sum = a.x + a.y + a.z + a.w + c.x + c.y + c.z + c.w;
#pragma unroll
  for (int s = 16; s; s >>= 1) sum += __shfl_xor_sync(~0u, sum, s);
  float mu = sum * (1.f / kH);
  float d0 = a.x - mu, d1 = a.y - mu, d2 = a.z - mu, d3 = a.w - mu;
  float d4 = c.x - mu, d5 = c.y - mu, d6 = c.z - mu, d7 = c.w - mu;
  float sq = d0 * d0 + d1 * d1 + d2 * d2 + d3 * d3 + d4 * d4 + d5 * d5 +
             d6 * d6 + d7 * d7;
#pragma unroll
  for (int s = 16; s; s >>= 1) sq += __shfl_xor_sync(~0u, sq, s);
  float inv = rsqrtf(sq * (1.f / kH) + 1e-5f);
  float4 w0 = *(const float4*)(w + lane * 4);
  float4 w1 = *(const float4*)(w + 128 + lane * 4);
  float4 b0 = *(const float4*)(b + lane * 4);
  float4 b1 = *(const float4*)(b + 128 + lane * 4);
  float* xp = x + tok * kH;
  float4 o0 = {d0 * inv * w0.x + b0.x, d1 * inv * w0.y + b0.y,
               d2 * inv * w0.z + b0.z, d3 * inv * w0.w + b0.w};
  float4 o1 = {d4 * inv * w1.x + b1.x, d5 * inv * w1.y + b1.y,
               d6 * inv * w1.z + b1.z, d7 * inv * w1.w + b1.w};
  *(float4*)(xp + lane * 4) = o0;
  *(float4*)(xp + 128 + lane * 4) = o1;
}

// ---------------------------------------------------------------------------
// Output GEMM: out_pre[512,64] = x[512, 32768] @ W_out[64,32768]^T, split-K
// ---------------------------------------------------------------------------
constexpr int kKTotal = kN * kH;
constexpr int kKSplit = 16;
constexpr int kKChunk = kKTotal / kKSplit;

__global__ void zero_outpre() {
  int i = blockIdx.x * blockDim.x + threadIdx.x;
  if (i < kT * kOut) g_outpre[i] = 0.f;
}

__global__ void gemm_out_kernel(const float* __restrict__ Afull,
                                const float* __restrict__ Wout) {
  __shared__ float As[16][68];
  __shared__ float Bs[16][68];
  int m0 = blockIdx.y * 64;
  int kc0 = blockIdx.x * kKChunk;
  int tid = threadIdx.x;
  int tx = tid & 15, ty = tid >> 4;
  int lm = tid >> 2, lk = (tid & 3) * 4;
  float acc[4][4] = {};
  const float* Aptr = Afull + (size_t)(m0 + lm) * kKTotal + kc0 + lk;
  const float* Wptr = Wout + (size_t)lm * kKTotal + kc0 + lk;
  for (int k0 = 0; k0 < kKChunk; k0 += 16) {
    float4 av = *(const float4*)(Aptr + k0);
    float4 wv = *(const float4*)(Wptr + k0);
    As[lk + 0][lm] = av.x;
    As[lk + 1][lm] = av.y;
    As[lk + 2][lm] = av.z;
    As[lk + 3][lm] = av.w;
    Bs[lk + 0][lm] = wv.x;
    Bs[lk + 1][lm] = wv.y;
    Bs[lk + 2][lm] = wv.z;
    Bs[lk + 3][lm] = wv.w;
    __syncthreads();
#pragma unroll
    for (int k = 0; k < 16; ++k) {
      float4 a4 = *(const float4*)&As[k][ty * 4];
      float4 b4 = *(const float4*)&Bs[k][tx * 4];
      float a[4] = {a4.x, a4.y, a4.z, a4.w};
      float b[4] = {b4.x, b4.y, b4.z, b4.w};
#pragma unroll
      for (int i = 0; i < 4; ++i)
#pragma unroll
        for (int j = 0; j < 4; ++j) acc[i][j] += a[i] * b[j];
    }
    __syncthreads();
  }
#pragma unroll
  for (int i = 0; i < 4; ++i)
#pragma unroll
    for (int j = 0; j < 4; ++j)
      atomicAdd(&g_outpre[(m0 + ty * 4 + i) * kOut + tx * 4 + j], acc[i][j]);
}

__global__ void lnf_kernel(const float* __restrict__ b_out,
                           const float* __restrict__ w,
                           const float* __restrict__ bb,
                           float* __restrict__ out) {
  __shared__ float red[64];
  int t = blockIdx.x, o = threadIdx.x;
  float v = g_outpre[t * kOut + o] + b_out[o];
  red[o] = v;
  __syncthreads();
  for (int s = 32; s > 0; s >>= 1) {
    if (o < s) red[o] += red[o + s];
    __syncthreads();
  }
  float mu = red[0] * (1.f / kOut);
  __syncthreads();
  float d = v - mu;
  red[o] = d * d;
  __syncthreads();
  for (int s = 32; s > 0; s >>= 1) {
    if (o < s) red[o] += red[o + s];
    __syncthreads();
  }
  float var = red[0] * (1.f / kOut);
  out[t * kOut + o] = d * rsqrtf(var + 1e-5f) * w[o] + bb[o];
}

}  // namespace

extern "C" void kernel_launch(void* const* d_in, const int* in_sizes, int n_in,
                              void* d_out, int out_size) {
  const float* forest = (const float*)d_in[0];
  const int* adj = (const int*)d_in[1];
  const int* no = (const int*)d_in[2];
  const float* W_in = (const float*)d_in[3];
  const float* b_in = (const float*)d_in[4];
  const float* W_pos = (const float*)d_in[5];
  const float* b_pos = (const float*)d_in[6];
  const float* qkv_w = (const float*)d_in[7];
  const float* qkv_b = (const float*)d_in[8];
  const float* outp_w = (const float*)d_in[9];
  const float* outp_b = (const float*)d_in[10];
  const float* ln1_w = (const float*)d_in[11];
  const float* ln1_b = (const float*)d_in[12];
  const float* ff1_w = (const float*)d_in[13];
  const float* ff1_b = (const float*)d_in[14];
  const float* ff2_w = (const float*)d_in[15];
  const float* ff2_b = (const float*)d_in[16];
  const float* ln2_w = (const float*)d_in[17];
  const float* ln2_b = (const float*)d_in[18];
  const float* W_out = (const float*)d_in[19];
  const float* b_out = (const float*)d_in[20];
  const float* lnf_w = (const float*)d_in[21];
  const float* lnf_b = (const float*)d_in[22];
  float* out = (float*)d_out;

  float *px, *pqkv, *pattn, *pff, *py;
  cudaGetSymbolAddress((void**)&px, g_x);
  cudaGetSymbolAddress((void**)&pqkv, g_qkv);
  cudaGetSymbolAddress((void**)&pattn, g_attn);
  cudaGetSymbolAddress((void**)&pff, g_ff);
  cudaGetSymbolAddress((void**)&py, g_y);

  // launch index:            0
  prep_parent_kernel<<<(kTN + 255) / 256, 256>>>(adj);
  // launch index:            1  (maxno + wpos transpose fused)
  prep2_kernel<<<kT + (kP * kH + 255) / 256, 256>>>(no, W_pos);
  // launch index:            2
  embed_kernel<<<kTN / 32, 256>>>(forest, no, W_in, b_in, b_pos);

  dim3 blk(256);
  for (int l = 0; l < kL; ++l) {
    // launch index 3 on l==0: ncu -s profiles this (qkv GEMM).
    gemm_tc<EPI_BIAS><<<dim3((3 * kH) / 128, kTN / 128), blk>>>(
        px, qkv_w + (size_t)l * 3 * kH * kH, qkv_b + (size_t)l * 3 * kH,
        nullptr, pqkv, kTN, 3 * kH, kH);
    attn_kernel<<<kT * kHeads, 128>>>(pqkv, pattn);
    gemm_tc<EPI_RES><<<dim3(kH / 128, kTN / 128), blk>>>(
        pattn, outp_w + (size_t)l * kH * kH, outp_b + (size_t)l * kH, px, py,
        kTN, kH, kH);
    ln_kernel<<<kTN / 8, 256>>>(py, ln1_w + (size_t)l * kH,
                                ln1_b + (size_t)l * kH, px);
    gemm_tc<EPI_RELU><<<dim3(kFF / 128, kTN / 128), blk>>>(
        px, ff1_w + (size_t)l * kFF * kH, ff1_b + (size_t)l * kFF, nullptr,
        pff, kTN, kFF, kH);
    gemm_tc<EPI_RES><<<dim3(kH / 128, kTN / 128), blk>>>(
        pff, ff2_w + (size_t)l * kH * kFF, ff2_b + (size_t)l * kH, px, py, kTN,
        kH, kFF);
    ln_kernel<<<kTN / 8, 256>>>(py, ln2_w + (size_t)l * kH,
                                ln2_b + (size_t)l * kH, px);
  }

  zero_outpre<<<(kT * kOut + 255) / 256, 256>>>();
  gemm_out_kernel<<<dim3(kKSplit, kT / 64), blk>>>(px, W_out);
  lnf_kernel<<<kT, kOut>>>(b_out, lnf_w, lnf_b, out);
}

// round 7
// speedup vs baseline: 1.3662x; 1.0955x over previous
#include <cuda_runtime.h>
#include <cuda_bf16.h>
#include <math.h>
#include <stdint.h>

namespace {

constexpr int kN = 128, kF = 16, kH = 256, kHeads = 4, kFF = 512,
              kOut = 64, kBF = 3, kL = 2, kP = 384, kT = 512, kE = 127,
              kDH = 64, kTN = kT * kN;

// ---- static device scratch (allocation-free) ----
__device__ float g_x[kTN * kH];          // 64 MB
__device__ float g_qkv[kTN * 3 * kH];    // 192 MB
__device__ float g_attn[kTN * kH];       // 64 MB
__device__ float g_ff[kTN * kFF];        // 128 MB
__device__ float g_y[kTN * kH];          // 64 MB
__device__ float g_outpre[kT * kOut];
__device__ float g_WposT[kP * kH];       // transposed W_pos, [P][H]
__device__ int g_parent[kTN];
__device__ int g_slot[kTN];
__device__ int g_maxno[kT];

// ---------------------------------------------------------------------------
// Prep 1: parent/slot for every node.
// ---------------------------------------------------------------------------
__global__ void prep_parent_kernel(const int* __restrict__ adj) {
  int i = blockIdx.x * blockDim.x + threadIdx.x;
  if (i >= kTN) return;
  int local = i & (kN - 1);
  int tree = i >> 7;
  int par = -1, sl = 0;
  if (local != 0) {
    int e = tree * kE + local - 1;
    int p = adj[3 * e], c = adj[3 * e + 1], s = adj[3 * e + 2];
    if (c == i && p >= 0) {
      par = p;
      sl = s;
    }
  }
  g_parent[i] = par;
  g_slot[i] = sl;
}

// ---------------------------------------------------------------------------
// Prep 2: fused per-tree max(node_order) + W_pos transpose.
// ---------------------------------------------------------------------------
__global__ void prep2_kernel(const int* __restrict__ no,
                             const float* __restrict__ W_pos) {
  if (blockIdx.x < kT) {
    __shared__ int red[128];
    int t = blockIdx.x;
    if (threadIdx.x < 128) red[threadIdx.x] = no[t * kN + threadIdx.x];
    __syncthreads();
    for (int s = 64; s > 0; s >>= 1) {
      if (threadIdx.x < s)
        red[threadIdx.x] = max(red[threadIdx.x], red[threadIdx.x + s]);
      __syncthreads();
    }
    if (threadIdx.x == 0) g_maxno[t] = red[0];
  } else {
    int i = (blockIdx.x - kT) * blockDim.x + threadIdx.x;
    if (i < kP * kH) {
      int p = i / kH, h = i % kH;
      g_WposT[p * kH + h] = W_pos[h * kP + p];
    }
  }
}

// ---------------------------------------------------------------------------
// Embedding: 32 tokens per block, coalesced W_posT access.
// ---------------------------------------------------------------------------
__global__ void embed_kernel(const float* __restrict__ forest,
                             const int* __restrict__ no,
                             const float* __restrict__ W_in,
                             const float* __restrict__ b_in,
                             const float* __restrict__ b_pos) {
  __shared__ float Wins[kF][kH];
  __shared__ float bib[kH];
  __shared__ float fs[32][kF];
  __shared__ int anc[32][8];
  __shared__ int cnt[32];
  int tid = threadIdx.x;
  int base = blockIdx.x * 32;
#pragma unroll
  for (int j = 0; j < kH * kF / 256; ++j) {
    int idx = tid + j * 256;
    int h = idx / kF, f = idx % kF;
    Wins[f][h] = W_in[idx];
  }
  bib[tid] = b_in[tid] + b_pos[tid];
  {
    int idx = tid;
    if (idx < 32 * kF) {
      int tk = idx / kF, f = idx % kF;
      fs[tk][f] = forest[(size_t)(base + tk) * kF + f];
    }
    idx = tid + 256;
    if (idx < 32 * kF) {
      int tk = idx / kF, f = idx % kF;
      fs[tk][f] = forest[(size_t)(base + tk) * kF + f];
    }
  }
  if (tid < 32) {
    int tok = base + tid;
    int tree = tok / kN;
    int mx = g_maxno[tree];
    int c = tok, n = 0;
    for (int it = 0; it < 8; ++it) {
      int p = g_parent[c];
      if (p < 0) break;
      int pd = mx - no[p];
      int s = g_slot[c] + 1;
      s = s < 0 ? 0 : (s > kBF - 1 ? kBF - 1 : s);
      int idx = pd * kBF + s;
      if (idx >= 0 && idx < kP) anc[tid][n++] = idx;
      c = p;
    }
    cnt[tid] = n;
  }
  __syncthreads();
  int h = tid;
  for (int tk = 0; tk < 32; ++tk) {
    float acc = bib[h];
#pragma unroll
    for (int f = 0; f < kF; ++f) acc += fs[tk][f] * Wins[f][h];
    int c = cnt[tk];
    for (int a = 0; a < c; ++a) acc += g_WposT[anc[tk][a] * kH + h];
    g_x[(size_t)(base + tk) * kH + h] = acc;
  }
}

// ---------------------------------------------------------------------------
// bf16 mma helpers
// ---------------------------------------------------------------------------
enum { EPI_BIAS = 0, EPI_RELU = 1, EPI_RES = 2 };

__device__ __forceinline__ uint32_t pack_bf16(float x, float y) {
  __nv_bfloat162 h = __floats2bfloat162_rn(x, y);
  return *reinterpret_cast<uint32_t*>(&h);
}

__device__ __forceinline__ void mma_bf16(float* c, const uint32_t* a,
                                         const uint32_t* b) {
  asm("mma.sync.aligned.m16n8k16.row.col.f32.bf16.bf16.f32 "
      "{%0,%1,%2,%3},{%4,%5,%6,%7},{%8,%9},{%0,%1,%2,%3};"
      : "+f"(c[0]), "+f"(c[1]), "+f"(c[2]), "+f"(c[3])
      : "r"(a[0]), "r"(a[1]), "r"(a[2]), "r"(a[3]), "r"(b[0]), "r"(b[1]));
}

// ---------------------------------------------------------------------------
// bf16 tensor-core GEMM: C[M,Nd] = A[M,K] @ W[Nd,K]^T + bias (+relu|+res)
// CTA tile 128x128x32, 8 warps. Smem u32[128][20] (2 bf16 per u32),
// stride 20 -> all 32 banks distinct for fragment loads.
// fp32 global in, converted at STS; fp32 accumulate; fp32 epilogue.
// ---------------------------------------------------------------------------
template <int EPI>
__global__ __launch_bounds__(256) void gemm_tc(const float* __restrict__ A,
                                               const float* __restrict__ W,
                                               const float* __restrict__ bias,
                                               const float* __restrict__ res,
                                               float* __restrict__ C, int M,
                                               int Nd, int K) {
  __shared__ uint32_t As[128][20];
  __shared__ uint32_t Bs[128][20];
  int tid = threadIdx.x;
  int lane = tid & 31, warp = tid >> 5;
  int g = lane >> 2, tg = lane & 3;
  int wm = (warp & 1) * 64;
  int wn = (warp >> 1) * 32;
  int m0 = blockIdx.y * 128, n0 = blockIdx.x * 128;

  int lr = tid >> 3;        // 0..31 row within pass
  int lk8 = tid & 7;        // which float4 of the 32-k tile

  float acc[4][4][4];
#pragma unroll
  for (int i = 0; i < 4; ++i)
#pragma unroll
    for (int j = 0; j < 4; ++j)
#pragma unroll
      for (int c = 0; c < 4; ++c) acc[i][j][c] = 0.f;

  const float* Ag = A + (size_t)(m0 + lr) * K + lk8 * 4;
  const float* Wg = W + (size_t)(n0 + lr) * K + lk8 * 4;

  float4 ra[4], rb[4];
#pragma unroll
  for (int p = 0; p < 4; ++p) {
    ra[p] = *(const float4*)(Ag + (size_t)(32 * p) * K);
    rb[p] = *(const float4*)(Wg + (size_t)(32 * p) * K);
  }

  for (int k0 = 0;;) {
#pragma unroll
    for (int p = 0; p < 4; ++p) {
      uint2 av = {pack_bf16(ra[p].x, ra[p].y), pack_bf16(ra[p].z, ra[p].w)};
      uint2 bv = {pack_bf16(rb[p].x, rb[p].y), pack_bf16(rb[p].z, rb[p].w)};
      *(uint2*)&As[lr + 32 * p][lk8 * 2] = av;
      *(uint2*)&Bs[lr + 32 * p][lk8 * 2] = bv;
    }
    __syncthreads();
    k0 += 32;
    bool more = k0 < K;
    if (more) {
#pragma unroll
      for (int p = 0; p < 4; ++p) {
        ra[p] = *(const float4*)(Ag + (size_t)(32 * p) * K + k0);
        rb[p] = *(const float4*)(Wg + (size_t)(32 * p) * K + k0);
      }
    }
#pragma unroll
    for (int ks = 0; ks < 2; ++ks) {
      int kb = ks * 8;  // u32 cols per k16 step
      uint32_t af[4][4], bf[4][2];
#pragma unroll
      for (int mi = 0; mi < 4; ++mi) {
        int r = wm + mi * 16 + g;
        af[mi][0] = As[r][kb + tg];
        af[mi][1] = As[r + 8][kb + tg];
        af[mi][2] = As[r][kb + tg + 4];
        af[mi][3] = As[r + 8][kb + tg + 4];
      }
#pragma unroll
      for (int nj = 0; nj < 4; ++nj) {
        int c = wn + nj * 8 + g;
        bf[nj][0] = Bs[c][kb + tg];
        bf[nj][1] = Bs[c][kb + tg + 4];
      }
#pragma unroll
      for (int mi = 0; mi < 4; ++mi)
#pragma unroll
        for (int nj = 0; nj < 4; ++nj) mma_bf16(acc[mi][nj], af[mi], bf[nj]);
    }
    if (!more) break;
    __syncthreads();
  }

#pragma unroll
  for (int nj = 0; nj < 4; ++nj) {
    int col = n0 + wn + nj * 8 + tg * 2;
    float b0 = bias[col], b1 = bias[col + 1];
#pragma unroll
    for (int mi = 0; mi < 4; ++mi) {
      int row = m0 + wm + mi * 16 + g;
      float v00 = acc[mi][nj][0] + b0;
      float v01 = acc[mi][nj][1] + b1;
      float v10 = acc[mi][nj][2] + b0;
      float v11 = acc[mi][nj][3] + b1;
      if (EPI == EPI_RELU) {
        v00 = fmaxf(v00, 0.f);
        v01 = fmaxf(v01, 0.f);
        v10 = fmaxf(v10, 0.f);
        v11 = fmaxf(v11, 0.f);
      }
      if (EPI == EPI_RES) {
        float2 r0 = *(const float2*)(res + (size_t)row * Nd + col);
        float2 r1 = *(const float2*)(res + (size_t)(row + 8) * Nd + col);
        v00 += r0.x;
        v01 += r0.y;
        v10 += r1.x;
        v11 += r1.y;
      }
      float2 o0 = {v00, v01}, o1 = {v10, v11};
      *(float2*)(C + (size_t)row * Nd + col) = o0;
      *(float2*)(C + (size_t)(row + 8) * Nd + col) = o1;
    }
  }
}

// ---------------------------------------------------------------------------
// Attention (scalar): block per (tree, head), thread per query,
// online softmax with skip-rescale fast path.
// ---------------------------------------------------------------------------
__global__ void attn_kernel(const float* __restrict__ qkv,
                            float* __restrict__ out) {
  int t = blockIdx.x >> 2;
  int h = blockIdx.x & 3;
  int qi = threadIdx.x;
  __shared__ float Ks[64][64];
  __shared__ float Vs[64][64];
  const size_t base = (size_t)t * kN * (3 * kH);
  const float* qrow = qkv + base + (size_t)qi * (3 * kH) + h * kDH;
  float q[64];
#pragma unroll
  for (int d4 = 0; d4 < 16; ++d4) {
    float4 v = *(const float4*)(qrow + d4 * 4);
    q[d4 * 4 + 0] = v.x;
    q[d4 * 4 + 1] = v.y;
    q[d4 * 4 + 2] = v.z;
    q[d4 * 4 + 3] = v.w;
  }
  float m = -1e30f, l = 0.f;
  float o[64];
#pragma unroll
  for (int d = 0; d < 64; ++d) o[d] = 0.f;
  const float scale = 0.125f;
  for (int kt = 0; kt < 2; ++kt) {
    for (int idx = threadIdx.x; idx < 64 * 16; idx += 128) {
      int r = idx >> 4, d4 = idx & 15;
      const float* kp =
          qkv + base + (size_t)(kt * 64 + r) * (3 * kH) + kH + h * kDH + d4 * 4;
      const float* vp = qkv + base + (size_t)(kt * 64 + r) * (3 * kH) +
                        2 * kH + h * kDH + d4 * 4;
      *(float4*)&Ks[r][d4 * 4] = *(const float4*)kp;
      *(float4*)&Vs[r][d4 * 4] = *(const float4*)vp;
    }
    __syncthreads();
    for (int j = 0; j < 64; ++j) {
      float s = 0.f;
#pragma unroll
      for (int d = 0; d < 64; ++d) s += q[d] * Ks[j][d];
      s *= scale;
      if (s <= m) {
        float p = __expf(s - m);
        l += p;
#pragma unroll
        for (int d = 0; d < 64; ++d) o[d] += p * Vs[j][d];
      } else {
        float corr = __expf(m - s);
        l = l * corr + 1.f;
#pragma unroll
        for (int d = 0; d < 64; ++d) o[d] = o[d] * corr + Vs[j][d];
        m = s;
      }
    }
    __syncthreads();
  }
  float inv = 1.f / l;
  float* op = out + (size_t)(t * kN + qi) * kH + h * kDH;
#pragma unroll
  for (int d4 = 0; d4 < 16; ++d4) {
    float4 v;
    v.x = o[d4 * 4 + 0] * inv;
    v.y = o[d4 * 4 + 1] * inv;
    v.z = o[d4 * 4 + 2] * inv;
    v.w = o[d4 * 4 + 3] * inv;
    *(float4*)(op + d4 * 4) = v;
  }
}

// ---------------------------------------------------------------------------
// LayerNorm: warp per token, 8 tokens per block, shuffle reductions.
// ---------------------------------------------------------------------------
__global__ __launch_bounds__(256) void ln_kernel(const float* __restrict__ y,
                                                 const float* __restrict__ w,
                                                 const float* __restrict__ b,
                                                 float* __restrict__ x) {
  int warp = threadIdx.x >> 5, lane = threadIdx.x & 31;
  size_t tok = (size_t)blockIdx.x * 8 + warp;
  const float* yp = y + tok * kH;
  float4 a = *(const float4*)(yp + lane * 4);
  float4 c = *(const float4*)(yp + 128 + lane * 4);
  float sum = a.x + a.y + a.z + a.w + c.x + c.y + c.z + c.w;
#pragma unroll
  for (int s = 16; s; s >>= 1) sum += __shfl_xor_sync(~0u, sum, s);
  float mu = sum * (1.f / kH);
  float d0 = a.x - mu, d1 = a.y - mu, d2 = a.z - mu, d3 = a.w - mu;
  float d4 = c.x - mu, d5 = c.y - mu, d6 = c.z - mu, d7 = c.w - mu;
  float sq = d0 * d0 + d1 * d1 + d2 * d2 + d3 * d3 + d4 * d4 + d5 * d5 +
             d6 * d6 + d7 * d7;
#pragma unroll
  for (int s = 16; s; s >>= 1) sq += __shfl_xor_sync(~0u, sq, s);
  float inv = rsqrtf(sq * (1.f / kH) + 1e-5f);
  float4 w0 = *(const float4*)(w + lane * 4);
  float4 w1 = *(const float4*)(w + 128 + lane * 4);
  float4 b0 = *(const float4*)(b + lane * 4);
  float4 b1 = *(const float4*)(b + 128 + lane * 4);
  float* xp = x + tok * kH;
  float4 o0 = {d0 * inv * w0.x + b0.x, d1 * inv * w0.y + b0.y,
               d2 * inv * w0.z + b0.z, d3 * inv * w0.w + b0.w};
  float4 o1 = {d4 * inv * w1.x + b1.x, d5 * inv * w1.y + b1.y,
               d6 * inv * w1.z + b1.z, d7 * inv * w1.w + b1.w};
  *(float4*)(xp + lane * 4) = o0;
  *(float4*)(xp + 128 + lane * 4) = o1;
}

// ---------------------------------------------------------------------------
// Output GEMM: out_pre[512,64] = x[512, 32768] @ W_out[64,32768]^T, split-K
// ---------------------------------------------------------------------------
constexpr int kKTotal = kN * kH;
constexpr int kKSplit = 16;
constexpr int kKChunk = kKTotal / kKSplit;

__global__ void zero_outpre() {
  int i = blockIdx.x * blockDim.x + threadIdx.x;
  if (i < kT * kOut) g_outpre[i] = 0.f;
}

__global__ void gemm_out_kernel(const float* __restrict__ Afull,
                                const float* __restrict__ Wout) {
  __shared__ float As[16][68];
  __shared__ float Bs[16][68];
  int m0 = blockIdx.y * 64;
  int kc0 = blockIdx.x * kKChunk;
  int tid = threadIdx.x;
  int tx = tid & 15, ty = tid >> 4;
  int lm = tid >> 2, lk = (tid & 3) * 4;
  float acc[4][4] = {};
  const float* Aptr = Afull + (size_t)(m0 + lm) * kKTotal + kc0 + lk;
  const float* Wptr = Wout + (size_t)lm * kKTotal + kc0 + lk;
  for (int k0 = 0; k0 < kKChunk; k0 += 16) {
    float4 av = *(const float4*)(Aptr + k0);
    float4 wv = *(const float4*)(Wptr + k0);
    As[lk + 0][lm] = av.x;
    As[lk + 1][lm] = av.y;
    As[lk + 2][lm] = av.z;
    As[lk + 3][lm] = av.w;
    Bs[lk + 0][lm] = wv.x;
    Bs[lk + 1][lm] = wv.y;
    Bs[lk + 2][lm] = wv.z;
    Bs[lk + 3][lm] = wv.w;
    __syncthreads();
#pragma unroll
    for (int k = 0; k < 16; ++k) {
      float4 a4 = *(const float4*)&As[k][ty * 4];
      float4 b4 = *(const float4*)&Bs[k][tx * 4];
      float a[4] = {a4.x, a4.y, a4.z, a4.w};
      float b[4] = {b4.x, b4.y, b4.z, b4.w};
#pragma unroll
      for (int i = 0; i < 4; ++i)
#pragma unroll
        for (int j = 0; j < 4; ++j) acc[i][j] += a[i] * b[j];
    }
    __syncthreads();
  }
#pragma unroll
  for (int i = 0; i < 4; ++i)
#pragma unroll
    for (int j = 0; j < 4; ++j)
      atomicAdd(&g_outpre[(m0 + ty * 4 + i) * kOut + tx * 4 + j], acc[i][j]);
}

__global__ void lnf_kernel(const float* __restrict__ b_out,
                           const float* __restrict__ w,
                           const float* __restrict__ bb,
                           float* __restrict__ out) {
  __shared__ float red[64];
  int t = blockIdx.x, o = threadIdx.x;
  float v = g_outpre[t * kOut + o] + b_out[o];
  red[o] = v;
  __syncthreads();
  for (int s = 32; s > 0; s >>= 1) {
    if (o < s) red[o] += red[o + s];
    __syncthreads();
  }
  float mu = red[0] * (1.f / kOut);
  __syncthreads();
  float d = v - mu;
  red[o] = d * d;
  __syncthreads();
  for (int s = 32; s > 0; s >>= 1) {
    if (o < s) red[o] += red[o + s];
    __syncthreads();
  }
  float var = red[0] * (1.f / kOut);
  out[t * kOut + o] = d * rsqrtf(var + 1e-5f) * w[o] + bb[o];
}

}  // namespace

extern "C" void kernel_launch(void* const* d_in, const int* in_sizes, int n_in,
                              void* d_out, int out_size) {
  const float* forest = (const float*)d_in[0];
  const int* adj = (const int*)d_in[1];
  const int* no = (const int*)d_in[2];
  const float* W_in = (const float*)d_in[3];
  const float* b_in = (const float*)d_in[4];
  const float* W_pos = (const float*)d_in[5];
  const float* b_pos = (const float*)d_in[6];
  const float* qkv_w = (const float*)d_in[7];
  const float* qkv_b = (const float*)d_in[8];
  const float* outp_w = (const float*)d_in[9];
  const float* outp_b = (const float*)d_in[10];
  const float* ln1_w = (const float*)d_in[11];
  const float* ln1_b = (const float*)d_in[12];
  const float* ff1_w = (const float*)d_in[13];
  const float* ff1_b = (const float*)d_in[14];
  const float* ff2_w = (const float*)d_in[15];
  const float* ff2_b = (const float*)d_in[16];
  const float* ln2_w = (const float*)d_in[17];
  const float* ln2_b = (const float*)d_in[18];
  const float* W_out = (const float*)d_in[19];
  const float* b_out = (const float*)d_in[20];
  const float* lnf_w = (const float*)d_in[21];
  const float* lnf_b = (const float*)d_in[22];
  float* out = (float*)d_out;

  float *px, *pqkv, *pattn, *pff, *py;
  cudaGetSymbolAddress((void**)&px, g_x);
  cudaGetSymbolAddress((void**)&pqkv, g_qkv);
  cudaGetSymbolAddress((void**)&pattn, g_attn);
  cudaGetSymbolAddress((void**)&pff, g_ff);
  cudaGetSymbolAddress((void**)&py, g_y);

  // launch 0
  prep_parent_kernel<<<(kTN + 255) / 256, 256>>>(adj);
  // launch 1
  prep2_kernel<<<kT + (kP * kH + 255) / 256, 256>>>(no, W_pos);
  // launch 2
  embed_kernel<<<kTN / 32, 256>>>(forest, no, W_in, b_in, b_pos);

  dim3 blk(256);
  for (int l = 0; l < kL; ++l) {
    // launch 3 on l==0: ncu profiles this (qkv GEMM).
    gemm_tc<EPI_BIAS><<<dim3((3 * kH) / 128, kTN / 128), blk>>>(
        px, qkv_w + (size_t)l * 3 * kH * kH, qkv_b + (size_t)l * 3 * kH,
        nullptr, pqkv, kTN, 3 * kH, kH);
    attn_kernel<<<kT * kHeads, 128>>>(pqkv, pattn);
    gemm_tc<EPI_RES><<<dim3(kH / 128, kTN / 128), blk>>>(
        pattn, outp_w + (size_t)l * kH * kH, outp_b + (size_t)l * kH, px, py,
        kTN, kH, kH);
    ln_kernel<<<kTN / 8, 256>>>(py, ln1_w + (size_t)l * kH,
                                ln1_b + (size_t)l * kH, px);
    gemm_tc<EPI_RELU><<<dim3(kFF / 128, kTN / 128), blk>>>(
        px, ff1_w + (size_t)l * kFF * kH, ff1_b + (size_t)l * kFF, nullptr,
        pff, kTN, kFF, kH);
    gemm_tc<EPI_RES><<<dim3(kH / 128, kTN / 128), blk>>>(
        pff, ff2_w + (size_t)l * kH * kFF, ff2_b + (size_t)l * kH, px, py, kTN,
        kH, kFF);
    ln_kernel<<<kTN / 8, 256>>>(py, ln2_w + (size_t)l * kH,
                                ln2_b + (size_t)l * kH, px);
  }

  zero_outpre<<<(kT * kOut + 255) / 256, 256>>>();
  gemm_out_kernel<<<dim3(kKSplit, kT / 64), blk>>>(px, W_out);
  lnf_kernel<<<kT, kOut>>>(b_out, lnf_w, lnf_b, out);
}

// round 8
// speedup vs baseline: 1.4968x; 1.0956x over previous
#include <cuda_runtime.h>
#include <cuda_bf16.h>
#include <math.h>
#include <stdint.h>

namespace {

constexpr int kN = 128, kF = 16, kH = 256, kHeads = 4, kFF = 512,
              kOut = 64, kBF = 3, kL = 2, kP = 384, kT = 512, kE = 127,
              kDH = 64, kTN = kT * kN;

// ---- static device scratch (allocation-free) ----
__device__ float g_x[kTN * kH];
__device__ float g_qkv[kTN * 3 * kH];
__device__ float g_attn[kTN * kH];
__device__ float g_ff[kTN * kFF];
__device__ float g_y[kTN * kH];
__device__ float g_outpre[kT * kOut];
__device__ float g_WposT[kP * kH];
__device__ int g_parent[kTN];
__device__ int g_slot[kTN];
__device__ int g_maxno[kT];

// ---------------------------------------------------------------------------
// Prep 1: parent/slot for every node.
// ---------------------------------------------------------------------------
__global__ void prep_parent_kernel(const int* __restrict__ adj) {
  int i = blockIdx.x * blockDim.x + threadIdx.x;
  if (i >= kTN) return;
  int local = i & (kN - 1);
  int tree = i >> 7;
  int par = -1, sl = 0;
  if (local != 0) {
    int e = tree * kE + local - 1;
    int p = adj[3 * e], c = adj[3 * e + 1], s = adj[3 * e + 2];
    if (c == i && p >= 0) {
      par = p;
      sl = s;
    }
  }
  g_parent[i] = par;
  g_slot[i] = sl;
}

// ---------------------------------------------------------------------------
// Prep 2: fused per-tree max(node_order) + W_pos transpose.
// ---------------------------------------------------------------------------
__global__ void prep2_kernel(const int* __restrict__ no,
                             const float* __restrict__ W_pos) {
  if (blockIdx.x < kT) {
    __shared__ int red[128];
    int t = blockIdx.x;
    if (threadIdx.x < 128) red[threadIdx.x] = no[t * kN + threadIdx.x];
    __syncthreads();
    for (int s = 64; s > 0; s >>= 1) {
      if (threadIdx.x < s)
        red[threadIdx.x] = max(red[threadIdx.x], red[threadIdx.x + s]);
      __syncthreads();
    }
    if (threadIdx.x == 0) g_maxno[t] = red[0];
  } else {
    int i = (blockIdx.x - kT) * blockDim.x + threadIdx.x;
    if (i < kP * kH) {
      int p = i / kH, h = i % kH;
      g_WposT[p * kH + h] = W_pos[h * kP + p];
    }
  }
}

// ---------------------------------------------------------------------------
// Embedding: 32 tokens per block, coalesced W_posT access.
// ---------------------------------------------------------------------------
__global__ void embed_kernel(const float* __restrict__ forest,
                             const int* __restrict__ no,
                             const float* __restrict__ W_in,
                             const float* __restrict__ b_in,
                             const float* __restrict__ b_pos) {
  __shared__ float Wins[kF][kH];
  __shared__ float bib[kH];
  __shared__ float fs[32][kF];
  __shared__ int anc[32][8];
  __shared__ int cnt[32];
  int tid = threadIdx.x;
  int base = blockIdx.x * 32;
#pragma unroll
  for (int j = 0; j < kH * kF / 256; ++j) {
    int idx = tid + j * 256;
    int h = idx / kF, f = idx % kF;
    Wins[f][h] = W_in[idx];
  }
  bib[tid] = b_in[tid] + b_pos[tid];
  {
    int idx = tid;
    if (idx < 32 * kF) {
      int tk = idx / kF, f = idx % kF;
      fs[tk][f] = forest[(size_t)(base + tk) * kF + f];
    }
    idx = tid + 256;
    if (idx < 32 * kF) {
      int tk = idx / kF, f = idx % kF;
      fs[tk][f] = forest[(size_t)(base + tk) * kF + f];
    }
  }
  if (tid < 32) {
    int tok = base + tid;
    int tree = tok / kN;
    int mx = g_maxno[tree];
    int c = tok, n = 0;
    for (int it = 0; it < 8; ++it) {
      int p = g_parent[c];
      if (p < 0) break;
      int pd = mx - no[p];
      int s = g_slot[c] + 1;
      s = s < 0 ? 0 : (s > kBF - 1 ? kBF - 1 : s);
      int idx = pd * kBF + s;
      if (idx >= 0 && idx < kP) anc[tid][n++] = idx;
      c = p;
    }
    cnt[tid] = n;
  }
  __syncthreads();
  int h = tid;
  for (int tk = 0; tk < 32; ++tk) {
    float acc = bib[h];
#pragma unroll
    for (int f = 0; f < kF; ++f) acc += fs[tk][f] * Wins[f][h];
    int c = cnt[tk];
    for (int a = 0; a < c; ++a) acc += g_WposT[anc[tk][a] * kH + h];
    g_x[(size_t)(base + tk) * kH + h] = acc;
  }
}

// ---------------------------------------------------------------------------
// bf16 mma helpers
// ---------------------------------------------------------------------------
enum { EPI_BIAS = 0, EPI_RELU = 1, EPI_RES = 2 };

__device__ __forceinline__ uint32_t pack_bf16(float x, float y) {
  __nv_bfloat162 h = __floats2bfloat162_rn(x, y);
  return *reinterpret_cast<uint32_t*>(&h);
}

__device__ __forceinline__ void mma_bf16(float* c, const uint32_t* a,
                                         const uint32_t* b) {
  asm("mma.sync.aligned.m16n8k16.row.col.f32.bf16.bf16.f32 "
      "{%0,%1,%2,%3},{%4,%5,%6,%7},{%8,%9},{%0,%1,%2,%3};"
      : "+f"(c[0]), "+f"(c[1]), "+f"(c[2]), "+f"(c[3])
      : "r"(a[0]), "r"(a[1]), "r"(a[2]), "r"(a[3]), "r"(b[0]), "r"(b[1]));
}

__device__ __forceinline__ void ldmatrix_x4(uint32_t& r0, uint32_t& r1,
                                            uint32_t& r2, uint32_t& r3,
                                            uint32_t addr) {
  asm volatile(
      "ldmatrix.sync.aligned.m8n8.x4.shared.b16 {%0,%1,%2,%3}, [%4];"
      : "=r"(r0), "=r"(r1), "=r"(r2), "=r"(r3)
      : "r"(addr));
}

// ---------------------------------------------------------------------------
// bf16 tensor-core GEMM with ldmatrix fragments, 2 CTAs/SM.
// CTA tile 128x128x32, 8 warps. Smem u32[128][20], stride 20 (conflict-free
// for both STS pattern and ldmatrix phases).
// ---------------------------------------------------------------------------
template <int EPI>
__global__ __launch_bounds__(256, 2) void gemm_tc(
    const float* __restrict__ A, const float* __restrict__ W,
    const float* __restrict__ bias, const float* __restrict__ res,
    float* __restrict__ C, int M, int Nd, int K) {
  __shared__ uint32_t As[128][20];
  __shared__ uint32_t Bs[128][20];
  int tid = threadIdx.x;
  int lane = tid & 31, warp = tid >> 5;
  int g = lane >> 2, tg = lane & 3;
  int wm = (warp & 1) * 64;
  int wn = (warp >> 1) * 32;
  int m0 = blockIdx.y * 128, n0 = blockIdx.x * 128;

  int lr = tid >> 3;   // 0..31 row within pass
  int lk8 = tid & 7;   // which float4 of the 32-k tile

  float acc[4][4][4];
#pragma unroll
  for (int i = 0; i < 4; ++i)
#pragma unroll
    for (int j = 0; j < 4; ++j)
#pragma unroll
      for (int c = 0; c < 4; ++c) acc[i][j][c] = 0.f;

  const float* Ag = A + (size_t)(m0 + lr) * K + lk8 * 4;
  const float* Wg = W + (size_t)(n0 + lr) * K + lk8 * 4;

  // ldmatrix lane addressing (u32 offsets into [128][20] arrays)
  int a_row = wm + (lane & 7) + ((lane >> 3) & 1) * 8;
  int a_col = (lane >> 4) * 4;
  uint32_t a_base =
      (uint32_t)__cvta_generic_to_shared(&As[a_row][a_col]);
  int b_row = wn + (lane & 7) + (lane >> 4) * 8;
  int b_col = ((lane >> 3) & 1) * 4;
  uint32_t b_base =
      (uint32_t)__cvta_generic_to_shared(&Bs[b_row][b_col]);

  // prefetch (packed to bf16 immediately to save registers)
  uint2 pa[4], pb[4];
#pragma unroll
  for (int p = 0; p < 4; ++p) {
    float4 t = *(const float4*)(Ag + (size_t)(32 * p) * K);
    pa[p] = {pack_bf16(t.x, t.y), pack_bf16(t.z, t.w)};
    float4 u = *(const float4*)(Wg + (size_t)(32 * p) * K);
    pb[p] = {pack_bf16(u.x, u.y), pack_bf16(u.z, u.w)};
  }

  for (int k0 = 0;;) {
#pragma unroll
    for (int p = 0; p < 4; ++p) {
      *(uint2*)&As[lr + 32 * p][lk8 * 2] = pa[p];
      *(uint2*)&Bs[lr + 32 * p][lk8 * 2] = pb[p];
    }
    __syncthreads();
    k0 += 32;
    bool more = k0 < K;
    if (more) {
#pragma unroll
      for (int p = 0; p < 4; ++p) {
        float4 t = *(const float4*)(Ag + (size_t)(32 * p) * K + k0);
        pa[p] = {pack_bf16(t.x, t.y), pack_bf16(t.z, t.w)};
        float4 u = *(const float4*)(Wg + (size_t)(32 * p) * K + k0);
        pb[p] = {pack_bf16(u.x, u.y), pack_bf16(u.z, u.w)};
      }
    }
#pragma unroll
    for (int ks = 0; ks < 2; ++ks) {
      int kb = ks * 8;  // u32 col base of this k16 step
      uint32_t af[4][4], bf[4][2];
#pragma unroll
      for (int mi = 0; mi < 4; ++mi) {
        ldmatrix_x4(af[mi][0], af[mi][1], af[mi][2], af[mi][3],
                    a_base + (uint32_t)((mi * 16 * 20 + kb) * 4));
      }
#pragma unroll
      for (int p = 0; p < 2; ++p) {
        ldmatrix_x4(bf[p * 2][0], bf[p * 2][1], bf[p * 2 + 1][0],
                    bf[p * 2 + 1][1],
                    b_base + (uint32_t)((p * 16 * 20 + kb) * 4));
      }
#pragma unroll
      for (int mi = 0; mi < 4; ++mi)
#pragma unroll
        for (int nj = 0; nj < 4; ++nj) mma_bf16(acc[mi][nj], af[mi], bf[nj]);
    }
    if (!more) break;
    __syncthreads();
  }

#pragma unroll
  for (int nj = 0; nj < 4; ++nj) {
    int col = n0 + wn + nj * 8 + tg * 2;
    float b0 = bias[col], b1 = bias[col + 1];
#pragma unroll
    for (int mi = 0; mi < 4; ++mi) {
      int row = m0 + wm + mi * 16 + g;
      float v00 = acc[mi][nj][0] + b0;
      float v01 = acc[mi][nj][1] + b1;
      float v10 = acc[mi][nj][2] + b0;
      float v11 = acc[mi][nj][3] + b1;
      if (EPI == EPI_RELU) {
        v00 = fmaxf(v00, 0.f);
        v01 = fmaxf(v01, 0.f);
        v10 = fmaxf(v10, 0.f);
        v11 = fmaxf(v11, 0.f);
      }
      if (EPI == EPI_RES) {
        float2 r0 = *(const float2*)(res + (size_t)row * Nd + col);
        float2 r1 = *(const float2*)(res + (size_t)(row + 8) * Nd + col);
        v00 += r0.x;
        v01 += r0.y;
        v10 += r1.x;
        v11 += r1.y;
      }
      float2 o0 = {v00, v01}, o1 = {v10, v11};
      *(float2*)(C + (size_t)row * Nd + col) = o0;
      *(float2*)(C + (size_t)(row + 8) * Nd + col) = o1;
    }
  }
}

// ---------------------------------------------------------------------------
// Attention (scalar): block per (tree, head), thread per query,
// online softmax with skip-rescale fast path.
// ---------------------------------------------------------------------------
__global__ void attn_kernel(const float* __restrict__ qkv,
                            float* __restrict__ out) {
  int t = blockIdx.x >> 2;
  int h = blockIdx.x & 3;
  int qi = threadIdx.x;
  __shared__ float Ks[64][64];
  __shared__ float Vs[64][64];
  const size_t base = (size_t)t * kN * (3 * kH);
  const float* qrow = qkv + base + (size_t)qi * (3 * kH) + h * kDH;
  float q[64];
#pragma unroll
  for (int d4 = 0; d4 < 16; ++d4) {
    float4 v = *(const float4*)(qrow + d4 * 4);
    q[d4 * 4 + 0] = v.x;
    q[d4 * 4 + 1] = v.y;
    q[d4 * 4 + 2] = v.z;
    q[d4 * 4 + 3] = v.w;
  }
  float m = -1e30f, l = 0.f;
  float o[64];
#pragma unroll
  for (int d = 0; d < 64; ++d) o[d] = 0.f;
  const float scale = 0.125f;
  for (int kt = 0; kt < 2; ++kt) {
    for (int idx = threadIdx.x; idx < 64 * 16; idx += 128) {
      int r = idx >> 4, d4 = idx & 15;
      const float* kp =
          qkv + base + (size_t)(kt * 64 + r) * (3 * kH) + kH + h * kDH + d4 * 4;
      const float* vp = qkv + base + (size_t)(kt * 64 + r) * (3 * kH) +
                        2 * kH + h * kDH + d4 * 4;
      *(float4*)&Ks[r][d4 * 4] = *(const float4*)kp;
      *(float4*)&Vs[r][d4 * 4] = *(const float4*)vp;
    }
    __syncthreads();
    for (int j = 0; j < 64; ++j) {
      float s = 0.f;
#pragma unroll
      for (int d = 0; d < 64; ++d) s += q[d] * Ks[j][d];
      s *= scale;
      if (s <= m) {
        float p = __expf(s - m);
        l += p;
#pragma unroll
        for (int d = 0; d < 64; ++d) o[d] += p * Vs[j][d];
      } else {
        float corr = __expf(m - s);
        l = l * corr + 1.f;
#pragma unroll
        for (int d = 0; d < 64; ++d) o[d] = o[d] * corr + Vs[j][d];
        m = s;
      }
    }
    __syncthreads();
  }
  float inv = 1.f / l;
  float* op = out + (size_t)(t * kN + qi) * kH + h * kDH;
#pragma unroll
  for (int d4 = 0; d4 < 16; ++d4) {
    float4 v;
    v.x = o[d4 * 4 + 0] * inv;
    v.y = o[d4 * 4 + 1] * inv;
    v.z = o[d4 * 4 + 2] * inv;
    v.w = o[d4 * 4 + 3] * inv;
    *(float4*)(op + d4 * 4) = v;
  }
}

// ---------------------------------------------------------------------------
// LayerNorm: warp per token, 8 tokens per block, shuffle reductions.
// ---------------------------------------------------------------------------
__global__ __launch_bounds__(256) void ln_kernel(const float* __restrict__ y,
                                                 const float* __restrict__ w,
                                                 const float* __restrict__ b,
                                                 float* __restrict__ x) {
  int warp = threadIdx.x >> 5, lane = threadIdx.x & 31;
  size_t tok = (size_t)blockIdx.x * 8 + warp;
  const float* yp = y + tok * kH;
  float4 a = *(const float4*)(yp + lane * 4);
  float4 c = *(const float4*)(yp + 128 + lane * 4);
  float sum = a.x + a.y + a.z + a.w + c.x + c.y + c.z + c.w;
#pragma unroll
  for (int s = 16; s; s >>= 1) sum += __shfl_xor_sync(~0u, sum, s);
  float mu = sum * (1.f / kH);
  float d0 = a.x - mu, d1 = a.y - mu, d2 = a.z - mu, d3 = a.w - mu;
  float d4 = c.x - mu, d5 = c.y - mu, d6 = c.z - mu, d7 = c.w - mu;
  float sq = d0 * d0 + d1 * d1 + d2 * d2 + d3 * d3 + d4 * d4 + d5 * d5 +
             d6 * d6 + d7 * d7;
#pragma unroll
  for (int s = 16; s; s >>= 1) sq += __shfl_xor_sync(~0u, sq, s);
  float inv = rsqrtf(sq * (1.f / kH) + 1e-5f);
  float4 w0 = *(const float4*)(w + lane * 4);
  float4 w1 = *(const float4*)(w + 128 + lane * 4);
  float4 b0 = *(const float4*)(b + lane * 4);
  float4 b1 = *(const float4*)(b + 128 + lane * 4);
  float* xp = x + tok * kH;
  float4 o0 = {d0 * inv * w0.x + b0.x, d1 * inv * w0.y + b0.y,
               d2 * inv * w0.z + b0.z, d3 * inv * w0.w + b0.w};
  float4 o1 = {d4 * inv * w1.x + b1.x, d5 * inv * w1.y + b1.y,
               d6 * inv * w1.z + b1.z, d7 * inv * w1.w + b1.w};
  *(float4*)(xp + lane * 4) = o0;
  *(float4*)(xp + 128 + lane * 4) = o1;
}

// ---------------------------------------------------------------------------
// Output GEMM: out_pre[512,64] = x[512, 32768] @ W_out[64,32768]^T, split-K
// ---------------------------------------------------------------------------
constexpr int kKTotal = kN * kH;
constexpr int kKSplit = 16;
constexpr int kKChunk = kKTotal / kKSplit;

__global__ void zero_outpre() {
  int i = blockIdx.x * blockDim.x + threadIdx.x;
  if (i < kT * kOut) g_outpre[i] = 0.f;
}

__global__ void gemm_out_kernel(const float* __restrict__ Afull,
                                const float* __restrict__ Wout) {
  __shared__ float As[16][68];
  __shared__ float Bs[16][68];
  int m0 = blockIdx.y * 64;
  int kc0 = blockIdx.x * kKChunk;
  int tid = threadIdx.x;
  int tx = tid & 15, ty = tid >> 4;
  int lm = tid >> 2, lk = (tid & 3) * 4;
  float acc[4][4] = {};
  const float* Aptr = Afull + (size_t)(m0 + lm) * kKTotal + kc0 + lk;
  const float* Wptr = Wout + (size_t)lm * kKTotal + kc0 + lk;
  for (int k0 = 0; k0 < kKChunk; k0 += 16) {
    float4 av = *(const float4*)(Aptr + k0);
    float4 wv = *(const float4*)(Wptr + k0);
    As[lk + 0][lm] = av.x;
    As[lk + 1][lm] = av.y;
    As[lk + 2][lm] = av.z;
    As[lk + 3][lm] = av.w;
    Bs[lk + 0][lm] = wv.x;
    Bs[lk + 1][lm] = wv.y;
    Bs[lk + 2][lm] = wv.z;
    Bs[lk + 3][lm] = wv.w;
    __syncthreads();
#pragma unroll
    for (int k = 0; k < 16; ++k) {
      float4 a4 = *(const float4*)&As[k][ty * 4];
      float4 b4 = *(const float4*)&Bs[k][tx * 4];
      float a[4] = {a4.x, a4.y, a4.z, a4.w};
      float b[4] = {b4.x, b4.y, b4.z, b4.w};
#pragma unroll
      for (int i = 0; i < 4; ++i)
#pragma unroll
        for (int j = 0; j < 4; ++j) acc[i][j] += a[i] * b[j];
    }
    __syncthreads();
  }
#pragma unroll
  for (int i = 0; i < 4; ++i)
#pragma unroll
    for (int j = 0; j < 4; ++j)
      atomicAdd(&g_outpre[(m0 + ty * 4 + i) * kOut + tx * 4 + j], acc[i][j]);
}

__global__ void lnf_kernel(const float* __restrict__ b_out,
                           const float* __restrict__ w,
                           const float* __restrict__ bb,
                           float* __restrict__ out) {
  __shared__ float red[64];
  int t = blockIdx.x, o = threadIdx.x;
  float v = g_outpre[t * kOut + o] + b_out[o];
  red[o] = v;
  __syncthreads();
  for (int s = 32; s > 0; s >>= 1) {
    if (o < s) red[o] += red[o + s];
    __syncthreads();
  }
  float mu = red[0] * (1.f / kOut);
  __syncthreads();
  float d = v - mu;
  red[o] = d * d;
  __syncthreads();
  for (int s = 32; s > 0; s >>= 1) {
    if (o < s) red[o] += red[o + s];
    __syncthreads();
  }
  float var = red[0] * (1.f / kOut);
  out[t * kOut + o] = d * rsqrtf(var + 1e-5f) * w[o] + bb[o];
}

}  // namespace

extern "C" void kernel_launch(void* const* d_in, const int* in_sizes, int n_in,
                              void* d_out, int out_size) {
  const float* forest = (const float*)d_in[0];
  const int* adj = (const int*)d_in[1];
  const int* no = (const int*)d_in[2];
  const float* W_in = (const float*)d_in[3];
  const float* b_in = (const float*)d_in[4];
  const float* W_pos = (const float*)d_in[5];
  const float* b_pos = (const float*)d_in[6];
  const float* qkv_w = (const float*)d_in[7];
  const float* qkv_b = (const float*)d_in[8];
  const float* outp_w = (const float*)d_in[9];
  const float* outp_b = (const float*)d_in[10];
  const float* ln1_w = (const float*)d_in[11];
  const float* ln1_b = (const float*)d_in[12];
  const float* ff1_w = (const float*)d_in[13];
  const float* ff1_b = (const float*)d_in[14];
  const float* ff2_w = (const float*)d_in[15];
  const float* ff2_b = (const float*)d_in[16];
  const float* ln2_w = (const float*)d_in[17];
  const float* ln2_b = (const float*)d_in[18];
  const float* W_out = (const float*)d_in[19];
  const float* b_out = (const float*)d_in[20];
  const float* lnf_w = (const float*)d_in[21];
  const float* lnf_b = (const float*)d_in[22];
  float* out = (float*)d_out;

  float *px, *pqkv, *pattn, *pff, *py;
  cudaGetSymbolAddress((void**)&px, g_x);
  cudaGetSymbolAddress((void**)&pqkv, g_qkv);
  cudaGetSymbolAddress((void**)&pattn, g_attn);
  cudaGetSymbolAddress((void**)&pff, g_ff);
  cudaGetSymbolAddress((void**)&py, g_y);

  // launch 0
  prep_parent_kernel<<<(kTN + 255) / 256, 256>>>(adj);
  // launch 1
  prep2_kernel<<<kT + (kP * kH + 255) / 256, 256>>>(no, W_pos);
  // launch 2
  embed_kernel<<<kTN / 32, 256>>>(forest, no, W_in, b_in, b_pos);

  dim3 blk(256);
  for (int l = 0; l < kL; ++l) {
    // launch 3 on l==0: ncu profiles this (qkv GEMM).
    gemm_tc<EPI_BIAS><<<dim3((3 * kH) / 128, kTN / 128), blk>>>(
        px, qkv_w + (size_t)l * 3 * kH * kH, qkv_b + (size_t)l * 3 * kH,
        nullptr, pqkv, kTN, 3 * kH, kH);
    attn_kernel<<<kT * kHeads, 128>>>(pqkv, pattn);
    gemm_tc<EPI_RES><<<dim3(kH / 128, kTN / 128), blk>>>(
        pattn, outp_w + (size_t)l * kH * kH, outp_b + (size_t)l * kH, px, py,
        kTN, kH, kH);
    ln_kernel<<<kTN / 8, 256>>>(py, ln1_w + (size_t)l * kH,
                                ln1_b + (size_t)l * kH, px);
    gemm_tc<EPI_RELU><<<dim3(kFF / 128, kTN / 128), blk>>>(
        px, ff1_w + (size_t)l * kFF * kH, ff1_b + (size_t)l * kFF, nullptr,
        pff, kTN, kFF, kH);
    gemm_tc<EPI_RES><<<dim3(kH / 128, kTN / 128), blk>>>(
        pff, ff2_w + (size_t)l * kH * kFF, ff2_b + (size_t)l * kH, px, py, kTN,
        kH, kFF);
    ln_kernel<<<kTN / 8, 256>>>(py, ln2_w + (size_t)l * kH,
                                ln2_b + (size_t)l * kH, px);
  }

  zero_outpre<<<(kT * kOut + 255) / 256, 256>>>();
  gemm_out_kernel<<<dim3(kKSplit, kT / 64), blk>>>(px, W_out);
  lnf_kernel<<<kT, kOut>>>(b_out, lnf_w, lnf_b, out);
}

// round 11
// speedup vs baseline: 2.2214x; 1.4841x over previous
#include <cuda_runtime.h>
#include <cuda_bf16.h>
#include <math.h>
#include <stdint.h>

namespace {

constexpr int kN = 128, kF = 16, kH = 256, kHeads = 4, kFF = 512,
              kOut = 64, kBF = 3, kL = 2, kP = 384, kT = 512, kE = 127,
              kDH = 64, kTN = kT * kN;

// ---- static device scratch (allocation-free) ----
__device__ float g_x[kTN * kH];
__device__ float g_qkv[kTN * 3 * kH];
__device__ float g_attn[kTN * kH];
__device__ float g_ff[kTN * kFF];
__device__ float g_y[kTN * kH];
__device__ float g_outpre[kT * kOut];
__device__ float g_WposT[kP * kH];
__device__ int g_parent[kTN];
__device__ int g_slot[kTN];
__device__ int g_maxno[kT];

// ---------------------------------------------------------------------------
// Prep 1: parent/slot for every node.
// ---------------------------------------------------------------------------
__global__ void prep_parent_kernel(const int* __restrict__ adj) {
  int i = blockIdx.x * blockDim.x + threadIdx.x;
  if (i >= kTN) return;
  int local = i & (kN - 1);
  int tree = i >> 7;
  int par = -1, sl = 0;
  if (local != 0) {
    int e = tree * kE + local - 1;
    int p = adj[3 * e], c = adj[3 * e + 1], s = adj[3 * e + 2];
    if (c == i && p >= 0) {
      par = p;
      sl = s;
    }
  }
  g_parent[i] = par;
  g_slot[i] = sl;
}

// ---------------------------------------------------------------------------
// Prep 2: fused per-tree max(node_order) + W_pos transpose.
// ---------------------------------------------------------------------------
__global__ void prep2_kernel(const int* __restrict__ no,
                             const float* __restrict__ W_pos) {
  if (blockIdx.x < kT) {
    __shared__ int red[128];
    int t = blockIdx.x;
    if (threadIdx.x < 128) red[threadIdx.x] = no[t * kN + threadIdx.x];
    __syncthreads();
    for (int s = 64; s > 0; s >>= 1) {
      if (threadIdx.x < s)
        red[threadIdx.x] = max(red[threadIdx.x], red[threadIdx.x + s]);
      __syncthreads();
    }
    if (threadIdx.x == 0) g_maxno[t] = red[0];
  } else {
    int i = (blockIdx.x - kT) * blockDim.x + threadIdx.x;
    if (i < kP * kH) {
      int p = i / kH, h = i % kH;
      g_WposT[p * kH + h] = W_pos[h * kP + p];
    }
  }
}

// ---------------------------------------------------------------------------
// Embedding: 32 tokens per block, coalesced W_posT access.
// ---------------------------------------------------------------------------
__global__ void embed_kernel(const float* __restrict__ forest,
                             const int* __restrict__ no,
                             const float* __restrict__ W_in,
                             const float* __restrict__ b_in,
                             const float* __restrict__ b_pos) {
  __shared__ float Wins[kF][kH];
  __shared__ float bib[kH];
  __shared__ float fs[32][kF];
  __shared__ int anc[32][8];
  __shared__ int cnt[32];
  int tid = threadIdx.x;
  int base = blockIdx.x * 32;
#pragma unroll
  for (int j = 0; j < kH * kF / 256; ++j) {
    int idx = tid + j * 256;
    int h = idx / kF, f = idx % kF;
    Wins[f][h] = W_in[idx];
  }
  bib[tid] = b_in[tid] + b_pos[tid];
  {
    int idx = tid;
    if (idx < 32 * kF) {
      int tk = idx / kF, f = idx % kF;
      fs[tk][f] = forest[(size_t)(base + tk) * kF + f];
    }
    idx = tid + 256;
    if (idx < 32 * kF) {
      int tk = idx / kF, f = idx % kF;
      fs[tk][f] = forest[(size_t)(base + tk) * kF + f];
    }
  }
  if (tid < 32) {
    int tok = base + tid;
    int tree = tok / kN;
    int mx = g_maxno[tree];
    int c = tok, n = 0;
    for (int it = 0; it < 8; ++it) {
      int p = g_parent[c];
      if (p < 0) break;
      int pd = mx - no[p];
      int s = g_slot[c] + 1;
      s = s < 0 ? 0 : (s > kBF - 1 ? kBF - 1 : s);
      int idx = pd * kBF + s;
      if (idx >= 0 && idx < kP) anc[tid][n++] = idx;
      c = p;
    }
    cnt[tid] = n;
  }
  __syncthreads();
  int h = tid;
  for (int tk = 0; tk < 32; ++tk) {
    float acc = bib[h];
#pragma unroll
    for (int f = 0; f < kF; ++f) acc += fs[tk][f] * Wins[f][h];
    int c = cnt[tk];
    for (int a = 0; a < c; ++a) acc += g_WposT[anc[tk][a] * kH + h];
    g_x[(size_t)(base + tk) * kH + h] = acc;
  }
}

// ---------------------------------------------------------------------------
// bf16 mma helpers
// ---------------------------------------------------------------------------
enum { EPI_BIAS = 0, EPI_RELU = 1, EPI_RES = 2 };

__device__ __forceinline__ uint32_t pack_bf16(float x, float y) {
  __nv_bfloat162 h = __floats2bfloat162_rn(x, y);
  return *reinterpret_cast<uint32_t*>(&h);
}

__device__ __forceinline__ void mma_bf16(float* c, const uint32_t* a,
                                         const uint32_t* b) {
  asm("mma.sync.aligned.m16n8k16.row.col.f32.bf16.bf16.f32 "
      "{%0,%1,%2,%3},{%4,%5,%6,%7},{%8,%9},{%0,%1,%2,%3};"
      : "+f"(c[0]), "+f"(c[1]), "+f"(c[2]), "+f"(c[3])
      : "r"(a[0]), "r"(a[1]), "r"(a[2]), "r"(a[3]), "r"(b[0]), "r"(b[1]));
}

__device__ __forceinline__ void ldmatrix_x4(uint32_t& r0, uint32_t& r1,
                                            uint32_t& r2, uint32_t& r3,
                                            uint32_t addr) {
  asm volatile(
      "ldmatrix.sync.aligned.m8n8.x4.shared.b16 {%0,%1,%2,%3}, [%4];"
      : "=r"(r0), "=r"(r1), "=r"(r2), "=r"(r3)
      : "r"(addr));
}

// ---------------------------------------------------------------------------
// bf16 tensor-core GEMM with ldmatrix fragments, 2 CTAs/SM. (R7, passing)
// ---------------------------------------------------------------------------
template <int EPI>
__global__ __launch_bounds__(256, 2) void gemm_tc(
    const float* __restrict__ A, const float* __restrict__ W,
    const float* __restrict__ bias, const float* __restrict__ res,
    float* __restrict__ C, int M, int Nd, int K) {
  __shared__ uint32_t As[128][20];
  __shared__ uint32_t Bs[128][20];
  int tid = threadIdx.x;
  int lane = tid & 31, warp = tid >> 5;
  int g = lane >> 2, tg = lane & 3;
  int wm = (warp & 1) * 64;
  int wn = (warp >> 1) * 32;
  int m0 = blockIdx.y * 128, n0 = blockIdx.x * 128;

  int lr = tid >> 3;
  int lk8 = tid & 7;

  float acc[4][4][4];
#pragma unroll
  for (int i = 0; i < 4; ++i)
#pragma unroll
    for (int j = 0; j < 4; ++j)
#pragma unroll
      for (int c = 0; c < 4; ++c) acc[i][j][c] = 0.f;

  const float* Ag = A + (size_t)(m0 + lr) * K + lk8 * 4;
  const float* Wg = W + (size_t)(n0 + lr) * K + lk8 * 4;

  int a_row = wm + (lane & 7) + ((lane >> 3) & 1) * 8;
  int a_col = (lane >> 4) * 4;
  uint32_t a_base = (uint32_t)__cvta_generic_to_shared(&As[a_row][a_col]);
  int b_row = wn + (lane & 7) + (lane >> 4) * 8;
  int b_col = ((lane >> 3) & 1) * 4;
  uint32_t b_base = (uint32_t)__cvta_generic_to_shared(&Bs[b_row][b_col]);

  uint2 pa[4], pb[4];
#pragma unroll
  for (int p = 0; p < 4; ++p) {
    float4 t = *(const float4*)(Ag + (size_t)(32 * p) * K);
    pa[p] = {pack_bf16(t.x, t.y), pack_bf16(t.z, t.w)};
    float4 u = *(const float4*)(Wg + (size_t)(32 * p) * K);
    pb[p] = {pack_bf16(u.x, u.y), pack_bf16(u.z, u.w)};
  }

  for (int k0 = 0;;) {
#pragma unroll
    for (int p = 0; p < 4; ++p) {
      *(uint2*)&As[lr + 32 * p][lk8 * 2] = pa[p];
      *(uint2*)&Bs[lr + 32 * p][lk8 * 2] = pb[p];
    }
    __syncthreads();
    k0 += 32;
    bool more = k0 < K;
    if (more) {
#pragma unroll
      for (int p = 0; p < 4; ++p) {
        float4 t = *(const float4*)(Ag + (size_t)(32 * p) * K + k0);
        pa[p] = {pack_bf16(t.x, t.y), pack_bf16(t.z, t.w)};
        float4 u = *(const float4*)(Wg + (size_t)(32 * p) * K + k0);
        pb[p] = {pack_bf16(u.x, u.y), pack_bf16(u.z, u.w)};
      }
    }
#pragma unroll
    for (int ks = 0; ks < 2; ++ks) {
      int kb = ks * 8;
      uint32_t af[4][4], bf[4][2];
#pragma unroll
      for (int mi = 0; mi < 4; ++mi) {
        ldmatrix_x4(af[mi][0], af[mi][1], af[mi][2], af[mi][3],
                    a_base + (uint32_t)((mi * 16 * 20 + kb) * 4));
      }
#pragma unroll
      for (int p = 0; p < 2; ++p) {
        ldmatrix_x4(bf[p * 2][0], bf[p * 2][1], bf[p * 2 + 1][0],
                    bf[p * 2 + 1][1],
                    b_base + (uint32_t)((p * 16 * 20 + kb) * 4));
      }
#pragma unroll
      for (int mi = 0; mi < 4; ++mi)
#pragma unroll
        for (int nj = 0; nj < 4; ++nj) mma_bf16(acc[mi][nj], af[mi], bf[nj]);
    }
    if (!more) break;
    __syncthreads();
  }

#pragma unroll
  for (int nj = 0; nj < 4; ++nj) {
    int col = n0 + wn + nj * 8 + tg * 2;
    float b0 = bias[col], b1 = bias[col + 1];
#pragma unroll
    for (int mi = 0; mi < 4; ++mi) {
      int row = m0 + wm + mi * 16 + g;
      float v00 = acc[mi][nj][0] + b0;
      float v01 = acc[mi][nj][1] + b1;
      float v10 = acc[mi][nj][2] + b0;
      float v11 = acc[mi][nj][3] + b1;
      if (EPI == EPI_RELU) {
        v00 = fmaxf(v00, 0.f);
        v01 = fmaxf(v01, 0.f);
        v10 = fmaxf(v10, 0.f);
        v11 = fmaxf(v11, 0.f);
      }
      if (EPI == EPI_RES) {
        float2 r0 = *(const float2*)(res + (size_t)row * Nd + col);
        float2 r1 = *(const float2*)(res + (size_t)(row + 8) * Nd + col);
        v00 += r0.x;
        v01 += r0.y;
        v10 += r1.x;
        v11 += r1.y;
      }
      float2 o0 = {v00, v01}, o1 = {v10, v11};
      *(float2*)(C + (size_t)row * Nd + col) = o0;
      *(float2*)(C + (size_t)(row + 8) * Nd + col) = o1;
    }
  }
}

// ---------------------------------------------------------------------------
// bf16 tensor-core attention. One CTA per (tree,head), 8 warps, 2 CTAs/SM.
// Warp w owns S rows 16w..16w+15 in registers end-to-end:
//   S = Q@K^T (mma, 4 k-steps) -> quad-shuffle softmax -> pack P bf16 in
//   place in the accumulator -> O = P@V (mma, 8 k-steps, V^T in smem).
// Dynamic smem: Qs u32[128][36] | Ks u32[128][36] | Vt u32[64][68] = 54272 B.
// ---------------------------------------------------------------------------
constexpr int kQStr = 36;  // u32 per Q/K row (64 bf16 = 32 u32 + 4 pad)
constexpr int kVStr = 68;  // u32 per V^T row (128 keys bf16 = 64 u32 + 4 pad)
constexpr int kAttnSmem = (2 * 128 * kQStr + 64 * kVStr) * 4;  // 54272

__global__ __launch_bounds__(256, 2) void attn_tc(
    const float* __restrict__ qkv, float* __restrict__ out) {
  extern __shared__ uint32_t sm[];
  uint32_t* Qs = sm;
  uint32_t* Ks = sm + 128 * kQStr;
  uint32_t* Vt = sm + 2 * 128 * kQStr;
  int t = blockIdx.x >> 2, h = blockIdx.x & 3;
  int tid = threadIdx.x, lane = tid & 31, warp = tid >> 5;
  int g = lane >> 2, tg = lane & 3;
  const size_t base = (size_t)t * kN * (3 * kH);

  // ---- load Q, K (bf16) and V^T ----
  {
    int row = tid >> 1, part = tid & 1;  // 2 threads per row, 32 floats each
    const float* qp = qkv + base + (size_t)row * (3 * kH) + h * kDH + part * 32;
    const float* kp = qp + kH;
    uint32_t* qd = Qs + row * kQStr + part * 16;
    uint32_t* kd = Ks + row * kQStr + part * 16;
#pragma unroll
    for (int i = 0; i < 8; ++i) {
      float4 v = *(const float4*)(qp + i * 4);
      qd[i * 2] = pack_bf16(v.x, v.y);
      qd[i * 2 + 1] = pack_bf16(v.z, v.w);
      float4 w = *(const float4*)(kp + i * 4);
      kd[i * 2] = pack_bf16(w.x, w.y);
      kd[i * 2 + 1] = pack_bf16(w.z, w.w);
    }
    // V^T: Vt[dim][key] (bf16 scalar stores, one-time)
    const float* vp = qp + 2 * kH;
    __nv_bfloat16* vtb = (__nv_bfloat16*)Vt;
#pragma unroll
    for (int i = 0; i < 8; ++i) {
      float4 v = *(const float4*)(vp + i * 4);
      int d = part * 32 + i * 4;
      vtb[(d + 0) * (2 * kVStr) + row] = __float2bfloat16(v.x);
      vtb[(d + 1) * (2 * kVStr) + row] = __float2bfloat16(v.y);
      vtb[(d + 2) * (2 * kVStr) + row] = __float2bfloat16(v.z);
      vtb[(d + 3) * (2 * kVStr) + row] = __float2bfloat16(v.w);
    }
  }
  __syncthreads();

  // ---- S = Q @ K^T : warp rows 16w..16w+15, all 128 cols in registers ----
  float sacc[16][4];
#pragma unroll
  for (int nj = 0; nj < 16; ++nj)
#pragma unroll
    for (int c = 0; c < 4; ++c) sacc[nj][c] = 0.f;

  uint32_t a_base = (uint32_t)__cvta_generic_to_shared(
      Qs + (warp * 16 + (lane & 7) + ((lane >> 3) & 1) * 8) * kQStr +
      (lane >> 4) * 4);
  uint32_t k_base = (uint32_t)__cvta_generic_to_shared(
      Ks + ((lane & 7) + (lane >> 4) * 8) * kQStr + ((lane >> 3) & 1) * 4);

#pragma unroll
  for (int ks = 0; ks < 4; ++ks) {
    int kb = ks * 8;
    uint32_t af[4], bf[16][2];
    ldmatrix_x4(af[0], af[1], af[2], af[3], a_base + (uint32_t)(kb * 4));
#pragma unroll
    for (int p = 0; p < 8; ++p) {
      ldmatrix_x4(bf[p * 2][0], bf[p * 2][1], bf[p * 2 + 1][0],
                  bf[p * 2 + 1][1],
                  k_base + (uint32_t)((p * 16 * kQStr + kb) * 4));
    }
#pragma unroll
    for (int nj = 0; nj < 16; ++nj) mma_bf16(sacc[nj], af, bf[nj]);
  }

  // ---- softmax over rows r0=16w+g, r1=16w+8+g (quad shuffles) ----
  const float scale = 0.125f;
  float mx0 = -1e30f, mx1 = -1e30f;
#pragma unroll
  for (int nj = 0; nj < 16; ++nj) {
    mx0 = fmaxf(mx0, fmaxf(sacc[nj][0], sacc[nj][1]));
    mx1 = fmaxf(mx1, fmaxf(sacc[nj][2], sacc[nj][3]));
  }
  mx0 = fmaxf(mx0, __shfl_xor_sync(~0u, mx0, 1));
  mx0 = fmaxf(mx0, __shfl_xor_sync(~0u, mx0, 2));
  mx1 = fmaxf(mx1, __shfl_xor_sync(~0u, mx1, 1));
  mx1 = fmaxf(mx1, __shfl_xor_sync(~0u, mx1, 2));
  mx0 *= scale;
  mx1 *= scale;
  float sum0 = 0.f, sum1 = 0.f;
#pragma unroll
  for (int nj = 0; nj < 16; ++nj) {
    sacc[nj][0] = __expf(sacc[nj][0] * scale - mx0);
    sacc[nj][1] = __expf(sacc[nj][1] * scale - mx0);
    sacc[nj][2] = __expf(sacc[nj][2] * scale - mx1);
    sacc[nj][3] = __expf(sacc[nj][3] * scale - mx1);
    sum0 += sacc[nj][0] + sacc[nj][1];
    sum1 += sacc[nj][2] + sacc[nj][3];
  }
  sum0 += __shfl_xor_sync(~0u, sum0, 1);
  sum0 += __shfl_xor_sync(~0u, sum0, 2);
  sum1 += __shfl_xor_sync(~0u, sum1, 1);
  sum1 += __shfl_xor_sync(~0u, sum1, 2);
  float inv0 = 1.f / sum0, inv1 = 1.f / sum1;

  // pack P (bf16) in place: a-frag for k-step ks lives in
  // {sacc[2ks][0], sacc[2ks][1], sacc[2ks+1][0], sacc[2ks+1][1]} as bits.
  uint32_t pfrag[8][4];
#pragma unroll
  for (int ks = 0; ks < 8; ++ks) {
    pfrag[ks][0] = pack_bf16(sacc[2 * ks][0] * inv0, sacc[2 * ks][1] * inv0);
    pfrag[ks][1] = pack_bf16(sacc[2 * ks][2] * inv1, sacc[2 * ks][3] * inv1);
    pfrag[ks][2] =
        pack_bf16(sacc[2 * ks + 1][0] * inv0, sacc[2 * ks + 1][1] * inv0);
    pfrag[ks][3] =
        pack_bf16(sacc[2 * ks + 1][2] * inv1, sacc[2 * ks + 1][3] * inv1);
  }

  // ---- O = P @ V : n = 64 dims, k = 128 keys ----
  float oacc[8][4];
#pragma unroll
  for (int nj = 0; nj < 8; ++nj)
#pragma unroll
    for (int c = 0; c < 4; ++c) oacc[nj][c] = 0.f;

  uint32_t v_base = (uint32_t)__cvta_generic_to_shared(
      Vt + ((lane & 7) + (lane >> 4) * 8) * kVStr + ((lane >> 3) & 1) * 4);
#pragma unroll
  for (int ks = 0; ks < 8; ++ks) {
    int kb = ks * 8;
    uint32_t bf[8][2];
#pragma unroll
    for (int p = 0; p < 4; ++p) {
      ldmatrix_x4(bf[p * 2][0], bf[p * 2][1], bf[p * 2 + 1][0],
                  bf[p * 2 + 1][1],
                  v_base + (uint32_t)((p * 16 * kVStr + kb) * 4));
    }
#pragma unroll
    for (int nj = 0; nj < 8; ++nj) mma_bf16(oacc[nj], pfrag[ks], bf[nj]);
  }

  // ---- store O ----
  int r0 = warp * 16 + g, r1 = r0 + 8;
  float* op = out + (size_t)(t * kN) * kH + h * kDH;
#pragma unroll
  for (int nj = 0; nj < 8; ++nj) {
    int col = nj * 8 + tg * 2;
    float2 o0 = {oacc[nj][0], oacc[nj][1]};
    float2 o1 = {oacc[nj][2], oacc[nj][3]};
    *(float2*)(op + (size_t)r0 * kH + col) = o0;
    *(float2*)(op + (size_t)r1 * kH + col) = o1;
  }
}

// ---------------------------------------------------------------------------
// LayerNorm: warp per token, shuffle reductions.
// ---------------------------------------------------------------------------
__global__ __launch_bounds__(256) void ln_kernel(const float* __restrict__ y,
                                                 const float* __restrict__ w,
                                                 const float* __restrict__ b,
                                                 float* __restrict__ x) {
  int warp = threadIdx.x >> 5, lane = threadIdx.x & 31;
  size_t tok = (size_t)blockIdx.x * 8 + warp;
  const float* yp = y + tok * kH;
  float4 a = *(const float4*)(yp + lane * 4);
  float4 c = *(const float4*)(yp + 128 + lane * 4);
  float sum = a.x + a.y + a.z + a.w + c.x + c.y + c.z + c.w;
#pragma unroll
  for (int s = 16; s; s >>= 1) sum += __shfl_xor_sync(~0u, sum, s);
  float mu = sum * (1.f / kH);
  float d0 = a.x - mu, d1 = a.y - mu, d2 = a.z - mu, d3 = a.w - mu;
  float d4 = c.x - mu, d5 = c.y - mu, d6 = c.z - mu, d7 = c.w - mu;
  float sq = d0 * d0 + d1 * d1 + d2 * d2 + d3 * d3 + d4 * d4 + d5 * d5 +
             d6 * d6 + d7 * d7;
#pragma unroll
  for (int s = 16; s; s >>= 1) sq += __shfl_xor_sync(~0u, sq, s);
  float inv = rsqrtf(sq * (1.f / kH) + 1e-5f);
  float4 w0 = *(const float4*)(w + lane * 4);
  float4 w1 = *(const float4*)(w + 128 + lane * 4);
  float4 b0 = *(const float4*)(b + lane * 4);
  float4 b1 = *(const float4*)(b + 128 + lane * 4);
  float* xp = x + tok * kH;
  float4 o0 = {d0 * inv * w0.x + b0.x, d1 * inv * w0.y + b0.y,
               d2 * inv * w0.z + b0.z, d3 * inv * w0.w + b0.w};
  float4 o1 = {d4 * inv * w1.x + b1.x, d5 * inv * w1.y + b1.y,
               d6 * inv * w1.z + b1.z, d7 * inv * w1.w + b1.w};
  *(float4*)(xp + lane * 4) = o0;
  *(float4*)(xp + 128 + lane * 4) = o1;
}

// ---------------------------------------------------------------------------
// Output GEMM: out_pre[512,64] = x[512, 32768] @ W_out[64,32768]^T, split-K
// ---------------------------------------------------------------------------
constexpr int kKTotal = kN * kH;
constexpr int kKSplit = 16;
constexpr int kKChunk = kKTotal / kKSplit;

__global__ void zero_outpre() {
  int i = blockIdx.x * blockDim.x + threadIdx.x;
  if (i < kT * kOut) g_outpre[i] = 0.f;
}

__global__ void gemm_out_kernel(const float* __restrict__ Afull,
                                const float* __restrict__ Wout) {
  __shared__ float As[16][68];
  __shared__ float Bs[16][68];
  int m0 = blockIdx.y * 64;
  int kc0 = blockIdx.x * kKChunk;
  int tid = threadIdx.x;
  int tx = tid & 15, ty = tid >> 4;
  int lm = tid >> 2, lk = (tid & 3) * 4;
  float acc[4][4] = {};
  const float* Aptr = Afull + (size_t)(m0 + lm) * kKTotal + kc0 + lk;
  const float* Wptr = Wout + (size_t)lm * kKTotal + kc0 + lk;
  for (int k0 = 0; k0 < kKChunk; k0 += 16) {
    float4 av = *(const float4*)(Aptr + k0);
    float4 wv = *(const float4*)(Wptr + k0);
    As[lk + 0][lm] = av.x;
    As[lk + 1][lm] = av.y;
    As[lk + 2][lm] = av.z;
    As[lk + 3][lm] = av.w;
    Bs[lk + 0][lm] = wv.x;
    Bs[lk + 1][lm] = wv.y;
    Bs[lk + 2][lm] = wv.z;
    Bs[lk + 3][lm] = wv.w;
    __syncthreads();
#pragma unroll
    for (int k = 0; k < 16; ++k) {
      float4 a4 = *(const float4*)&As[k][ty * 4];
      float4 b4 = *(const float4*)&Bs[k][tx * 4];
      float a[4] = {a4.x, a4.y, a4.z, a4.w};
      float b[4] = {b4.x, b4.y, b4.z, b4.w};
#pragma unroll
      for (int i = 0; i < 4; ++i)
#pragma unroll
        for (int j = 0; j < 4; ++j) acc[i][j] += a[i] * b[j];
    }
    __syncthreads();
  }
#pragma unroll
  for (int i = 0; i < 4; ++i)
#pragma unroll
    for (int j = 0; j < 4; ++j)
      atomicAdd(&g_outpre[(m0 + ty * 4 + i) * kOut + tx * 4 + j], acc[i][j]);
}

__global__ void lnf_kernel(const float* __restrict__ b_out,
                           const float* __restrict__ w,
                           const float* __restrict__ bb,
                           float* __restrict__ out) {
  __shared__ float red[64];
  int t = blockIdx.x, o = threadIdx.x;
  float v = g_outpre[t * kOut + o] + b_out[o];
  red[o] = v;
  __syncthreads();
  for (int s = 32; s > 0; s >>= 1) {
    if (o < s) red[o] += red[o + s];
    __syncthreads();
  }
  float mu = red[0] * (1.f / kOut);
  __syncthreads();
  float d = v - mu;
  red[o] = d * d;
  __syncthreads();
  for (int s = 32; s > 0; s >>= 1) {
    if (o < s) red[o] += red[o + s];
    __syncthreads();
  }
  float var = red[0] * (1.f / kOut);
  out[t * kOut + o] = d * rsqrtf(var + 1e-5f) * w[o] + bb[o];
}

}  // namespace

extern "C" void kernel_launch(void* const* d_in, const int* in_sizes, int n_in,
                              void* d_out, int out_size) {
  const float* forest = (const float*)d_in[0];
  const int* adj = (const int*)d_in[1];
  const int* no = (const int*)d_in[2];
  const float* W_in = (const float*)d_in[3];
  const float* b_in = (const float*)d_in[4];
  const float* W_pos = (const float*)d_in[5];
  const float* b_pos = (const float*)d_in[6];
  const float* qkv_w = (const float*)d_in[7];
  const float* qkv_b = (const float*)d_in[8];
  const float* outp_w = (const float*)d_in[9];
  const float* outp_b = (const float*)d_in[10];
  const float* ln1_w = (const float*)d_in[11];
  const float* ln1_b = (const float*)d_in[12];
  const float* ff1_w = (const float*)d_in[13];
  const float* ff1_b = (const float*)d_in[14];
  const float* ff2_w = (const float*)d_in[15];
  const float* ff2_b = (const float*)d_in[16];
  const float* ln2_w = (const float*)d_in[17];
  const float* ln2_b = (const float*)d_in[18];
  const float* W_out = (const float*)d_in[19];
  const float* b_out = (const float*)d_in[20];
  const float* lnf_w = (const float*)d_in[21];
  const float* lnf_b = (const float*)d_in[22];
  float* out = (float*)d_out;

  float *px, *pqkv, *pattn, *pff, *py;
  cudaGetSymbolAddress((void**)&px, g_x);
  cudaGetSymbolAddress((void**)&pqkv, g_qkv);
  cudaGetSymbolAddress((void**)&pattn, g_attn);
  cudaGetSymbolAddress((void**)&pff, g_ff);
  cudaGetSymbolAddress((void**)&py, g_y);

  cudaFuncSetAttribute(attn_tc, cudaFuncAttributeMaxDynamicSharedMemorySize,
                       kAttnSmem);

  // launch 0
  prep_parent_kernel<<<(kTN + 255) / 256, 256>>>(adj);
  // launch 1
  prep2_kernel<<<kT + (kP * kH + 255) / 256, 256>>>(no, W_pos);
  // launch 2
  embed_kernel<<<kTN / 32, 256>>>(forest, no, W_in, b_in, b_pos);

  dim3 blk(256);
  for (int l = 0; l < kL; ++l) {
    // launch 3 on l==0: ncu profiles this (qkv GEMM).
    gemm_tc<EPI_BIAS><<<dim3((3 * kH) / 128, kTN / 128), blk>>>(
        px, qkv_w + (size_t)l * 3 * kH * kH, qkv_b + (size_t)l * 3 * kH,
        nullptr, pqkv, kTN, 3 * kH, kH);
    attn_tc<<<kT * kHeads, 256, kAttnSmem>>>(pqkv, pattn);
    gemm_tc<EPI_RES><<<dim3(kH / 128, kTN / 128), blk>>>(
        pattn, outp_w + (size_t)l * kH * kH, outp_b + (size_t)l * kH, px, py,
        kTN, kH, kH);
    ln_kernel<<<kTN / 8, 256>>>(py, ln1_w + (size_t)l * kH,
                                ln1_b + (size_t)l * kH, px);
    gemm_tc<EPI_RELU><<<dim3(kFF / 128, kTN / 128), blk>>>(
        px, ff1_w + (size_t)l * kFF * kH, ff1_b + (size_t)l * kFF, nullptr,
        pff, kTN, kFF, kH);
    gemm_tc<EPI_RES><<<dim3(kH / 128, kTN / 128), blk>>>(
        pff, ff2_w + (size_t)l * kH * kFF, ff2_b + (size_t)l * kH, px, py, kTN,
        kH, kFF);
    ln_kernel<<<kTN / 8, 256>>>(py, ln2_w + (size_t)l * kH,
                                ln2_b + (size_t)l * kH, px);
  }

  zero_outpre<<<(kT * kOut + 255) / 256, 256>>>();
  gemm_out_kernel<<<dim3(kKSplit, kT / 64), blk>>>(px, W_out);
  lnf_kernel<<<kT, kOut>>>(b_out, lnf_w, lnf_b, out);
}

// round 13
// speedup vs baseline: 2.9894x; 1.3457x over previous
#include <cuda_runtime.h>
#include <cuda_bf16.h>
#include <math.h>
#include <stdint.h>

namespace {

constexpr int kN = 128, kF = 16, kH = 256, kHeads = 4, kFF = 512,
              kOut = 64, kBF = 3, kL = 2, kP = 384, kT = 512, kE = 127,
              kDH = 64, kTN = kT * kN;

// ---- static device scratch (allocation-free) ----
__device__ float g_x[kTN * kH];                     // fp32 residual/LN state
__device__ float g_y[kTN * kH];                     // fp32 pre-LN temp
__device__ __nv_bfloat16 g_xb[kTN * kH];            // bf16 copy of x (GEMM A)
__device__ __nv_bfloat16 g_qkvb[kTN * 3 * kH];      // bf16 qkv
__device__ __nv_bfloat16 g_attnb[kTN * kH];         // bf16 attention out
__device__ __nv_bfloat16 g_ffb[kTN * kFF];          // bf16 ff1 out
__device__ __nv_bfloat16 g_wbf[1048576];            // all weights, bf16
__device__ float g_outpre[kT * kOut];
__device__ float g_WposT[kP * kH];
__device__ int g_parent[kTN];
__device__ int g_slot[kTN];
__device__ int g_maxno[kT];

// weight offsets inside g_wbf (elements)
constexpr int kWOffQkv = 0;                    // 2 x 768x256 = 393216
constexpr int kWOffOutp = 393216;              // 2 x 256x256 = 131072
constexpr int kWOffFf1 = 524288;               // 2 x 512x256 = 262144
constexpr int kWOffFf2 = 786432;               // 2 x 256x512 = 262144
constexpr int kWTotal = 1048576;

// ---------------------------------------------------------------------------
// Prep 1: parent/slot for every node.
// ---------------------------------------------------------------------------
__global__ void prep_parent_kernel(const int* __restrict__ adj) {
  int i = blockIdx.x * blockDim.x + threadIdx.x;
  if (i >= kTN) return;
  int local = i & (kN - 1);
  int tree = i >> 7;
  int par = -1, sl = 0;
  if (local != 0) {
    int e = tree * kE + local - 1;
    int p = adj[3 * e], c = adj[3 * e + 1], s = adj[3 * e + 2];
    if (c == i && p >= 0) {
      par = p;
      sl = s;
    }
  }
  g_parent[i] = par;
  g_slot[i] = sl;
}

// ---------------------------------------------------------------------------
// Prep 2: per-tree max(node_order) + W_pos transpose + weight bf16 convert.
// Blocks [0,kT): maxno. [kT, kT+384): transpose. [kT+384, ...): weights.
// ---------------------------------------------------------------------------
__global__ void prep2_kernel(const int* __restrict__ no,
                             const float* __restrict__ W_pos,
                             const float* __restrict__ qkv_w,
                             const float* __restrict__ outp_w,
                             const float* __restrict__ ff1_w,
                             const float* __restrict__ ff2_w) {
  if (blockIdx.x < kT) {
    __shared__ int red[128];
    int t = blockIdx.x;
    if (threadIdx.x < 128) red[threadIdx.x] = no[t * kN + threadIdx.x];
    __syncthreads();
    for (int s = 64; s > 0; s >>= 1) {
      if (threadIdx.x < s)
        red[threadIdx.x] = max(red[threadIdx.x], red[threadIdx.x + s]);
      __syncthreads();
    }
    if (threadIdx.x == 0) g_maxno[t] = red[0];
  } else if (blockIdx.x < kT + 384) {
    int i = (blockIdx.x - kT) * blockDim.x + threadIdx.x;
    if (i < kP * kH) {
      int p = i / kH, h = i % kH;
      g_WposT[p * kH + h] = W_pos[h * kP + p];
    }
  } else {
    int i = (blockIdx.x - kT - 384) * blockDim.x + threadIdx.x;
    if (i < kWTotal) {
      float v;
      if (i < kWOffOutp) v = qkv_w[i];
      else if (i < kWOffFf1) v = outp_w[i - kWOffOutp];
      else if (i < kWOffFf2) v = ff1_w[i - kWOffFf1];
      else v = ff2_w[i - kWOffFf2];
      g_wbf[i] = __float2bfloat16(v);
    }
  }
}

// ---------------------------------------------------------------------------
// Embedding: writes fp32 x and bf16 xb.
// ---------------------------------------------------------------------------
__global__ void embed_kernel(const float* __restrict__ forest,
                             const int* __restrict__ no,
                             const float* __restrict__ W_in,
                             const float* __restrict__ b_in,
                             const float* __restrict__ b_pos) {
  __shared__ float Wins[kF][kH];
  __shared__ float bib[kH];
  __shared__ float fs[32][kF];
  __shared__ int anc[32][8];
  __shared__ int cnt[32];
  int tid = threadIdx.x;
  int base = blockIdx.x * 32;
#pragma unroll
  for (int j = 0; j < kH * kF / 256; ++j) {
    int idx = tid + j * 256;
    int h = idx / kF, f = idx % kF;
    Wins[f][h] = W_in[idx];
  }
  bib[tid] = b_in[tid] + b_pos[tid];
  {
    int idx = tid;
    if (idx < 32 * kF) {
      int tk = idx / kF, f = idx % kF;
      fs[tk][f] = forest[(size_t)(base + tk) * kF + f];
    }
    idx = tid + 256;
    if (idx < 32 * kF) {
      int tk = idx / kF, f = idx % kF;
      fs[tk][f] = forest[(size_t)(base + tk) * kF + f];
    }
  }
  if (tid < 32) {
    int tok = base + tid;
    int tree = tok / kN;
    int mx = g_maxno[tree];
    int c = tok, n = 0;
    for (int it = 0; it < 8; ++it) {
      int p = g_parent[c];
      if (p < 0) break;
      int pd = mx - no[p];
      int s = g_slot[c] + 1;
      s = s < 0 ? 0 : (s > kBF - 1 ? kBF - 1 : s);
      int idx = pd * kBF + s;
      if (idx >= 0 && idx < kP) anc[tid][n++] = idx;
      c = p;
    }
    cnt[tid] = n;
  }
  __syncthreads();
  int h = tid;
  for (int tk = 0; tk < 32; ++tk) {
    float acc = bib[h];
#pragma unroll
    for (int f = 0; f < kF; ++f) acc += fs[tk][f] * Wins[f][h];
    int c = cnt[tk];
    for (int a = 0; a < c; ++a) acc += g_WposT[anc[tk][a] * kH + h];
    g_x[(size_t)(base + tk) * kH + h] = acc;
    g_xb[(size_t)(base + tk) * kH + h] = __float2bfloat16(acc);
  }
}

// ---------------------------------------------------------------------------
// mma / ldmatrix / cp.async helpers
// ---------------------------------------------------------------------------
enum { EPI_QKV_BF = 0, EPI_RELU_BF = 1, EPI_RES_F32 = 2 };

__device__ __forceinline__ uint32_t pack_bf16(float x, float y) {
  __nv_bfloat162 h = __floats2bfloat162_rn(x, y);
  return *reinterpret_cast<uint32_t*>(&h);
}

__device__ __forceinline__ void mma_bf16(float* c, const uint32_t* a,
                                         const uint32_t* b) {
  asm("mma.sync.aligned.m16n8k16.row.col.f32.bf16.bf16.f32 "
      "{%0,%1,%2,%3},{%4,%5,%6,%7},{%8,%9},{%0,%1,%2,%3};"
      : "+f"(c[0]), "+f"(c[1]), "+f"(c[2]), "+f"(c[3])
      : "r"(a[0]), "r"(a[1]), "r"(a[2]), "r"(a[3]), "r"(b[0]), "r"(b[1]));
}

__device__ __forceinline__ void ldmatrix_x4(uint32_t& r0, uint32_t& r1,
                                            uint32_t& r2, uint32_t& r3,
                                            uint32_t addr) {
  asm volatile(
      "ldmatrix.sync.aligned.m8n8.x4.shared.b16 {%0,%1,%2,%3}, [%4];"
      : "=r"(r0), "=r"(r1), "=r"(r2), "=r"(r3)
      : "r"(addr));
}

__device__ __forceinline__ void cp_async16(uint32_t saddr, const void* gaddr) {
  asm volatile("cp.async.cg.shared.global [%0], [%1], 16;" ::"r"(saddr),
               "l"(gaddr));
}
#define CP_COMMIT asm volatile("cp.async.commit_group;" ::: "memory")
#define CP_WAIT1 asm volatile("cp.async.wait_group 1;" ::: "memory")

// ---------------------------------------------------------------------------
// bf16 GEMM, cp.async double-buffered: C = A[M,K] @ W[Nd,K]^T + bias.
// A, W bf16 in global. Smem u32[2][128][20] per matrix (stage stride 10240 B).
// EPI_QKV_BF / EPI_RELU_BF write bf16 Cb; EPI_RES_F32 writes fp32 C (+res).
// ---------------------------------------------------------------------------
template <int EPI>
__global__ __launch_bounds__(256, 2) void gemm_bf(
    const __nv_bfloat16* __restrict__ A, const __nv_bfloat16* __restrict__ W,
    const float* __restrict__ bias, const float* __restrict__ res,
    float* __restrict__ C, __nv_bfloat16* __restrict__ Cb, int M, int Nd,
    int K) {
  __shared__ __align__(16) uint32_t As[2][128][20];
  __shared__ __align__(16) uint32_t Bs[2][128][20];
  int tid = threadIdx.x;
  int lane = tid & 31, warp = tid >> 5;
  int g = lane >> 2, tg = lane & 3;
  int wm = (warp & 1) * 64;
  int wn = (warp >> 1) * 32;
  int m0 = blockIdx.y * 128, n0 = blockIdx.x * 128;

  // cp.async mapping: chunk = 16 B (8 bf16); 512 chunks per tile, 2/thread.
  int rowA = tid >> 2, qA = tid & 3;
  uint32_t sOffA = (uint32_t)(rowA * 80 + qA * 16);  // + 5120 for second half
  uint32_t As0 = (uint32_t)__cvta_generic_to_shared(&As[0][0][0]);
  uint32_t Bs0 = (uint32_t)__cvta_generic_to_shared(&Bs[0][0][0]);

  float acc[4][4][4];
#pragma unroll
  for (int i = 0; i < 4; ++i)
#pragma unroll
    for (int j = 0; j < 4; ++j)
#pragma unroll
      for (int c = 0; c < 4; ++c) acc[i][j][c] = 0.f;

  auto issue = [&](int s, int kc) {
    const __nv_bfloat16* a1 =
        A + (size_t)(m0 + rowA) * K + kc * 32 + qA * 8;
    const __nv_bfloat16* w1 =
        W + (size_t)(n0 + rowA) * K + kc * 32 + qA * 8;
    uint32_t sa = As0 + s * 10240 + sOffA;
    uint32_t sb = Bs0 + s * 10240 + sOffA;
    cp_async16(sa, a1);
    cp_async16(sa + 5120, a1 + (size_t)64 * K);
    cp_async16(sb, w1);
    cp_async16(sb + 5120, w1 + (size_t)64 * K);
  };

  // ldmatrix lane addressing (stage 0 numeric bases)
  int a_row = wm + (lane & 7) + ((lane >> 3) & 1) * 8;
  int a_col = (lane >> 4) * 4;
  uint32_t a_base = (uint32_t)__cvta_generic_to_shared(&As[0][a_row][a_col]);
  int b_row = wn + (lane & 7) + (lane >> 4) * 8;
  int b_col = ((lane >> 3) & 1) * 4;
  uint32_t b_base = (uint32_t)__cvta_generic_to_shared(&Bs[0][b_row][b_col]);

  const int nk = K >> 5;
  issue(0, 0);
  CP_COMMIT;
  issue(1, 1);
  CP_COMMIT;

  for (int c = 0; c < nk; ++c) {
    int b = c & 1;
    CP_WAIT1;
    __syncthreads();
    uint32_t ab = a_base + b * 10240;
    uint32_t bb = b_base + b * 10240;
#pragma unroll
    for (int ks = 0; ks < 2; ++ks) {
      int kb = ks * 8;
      uint32_t af[4][4], bf[4][2];
#pragma unroll
      for (int mi = 0; mi < 4; ++mi) {
        ldmatrix_x4(af[mi][0], af[mi][1], af[mi][2], af[mi][3],
                    ab + (uint32_t)((mi * 16 * 20 + kb) * 4));
      }
#pragma unroll
      for (int p = 0; p < 2; ++p) {
        ldmatrix_x4(bf[p * 2][0], bf[p * 2][1], bf[p * 2 + 1][0],
                    bf[p * 2 + 1][1],
                    bb + (uint32_t)((p * 16 * 20 + kb) * 4));
      }
#pragma unroll
      for (int mi = 0; mi < 4; ++mi)
#pragma unroll
        for (int nj = 0; nj < 4; ++nj) mma_bf16(acc[mi][nj], af[mi], bf[nj]);
    }
    __syncthreads();
    if (c + 2 < nk) issue(b, c + 2);
    CP_COMMIT;
  }

  // epilogue
#pragma unroll
  for (int nj = 0; nj < 4; ++nj) {
    int col = n0 + wn + nj * 8 + tg * 2;
    float b0 = bias[col], b1 = bias[col + 1];
#pragma unroll
    for (int mi = 0; mi < 4; ++mi) {
      int row = m0 + wm + mi * 16 + g;
      float v00 = acc[mi][nj][0] + b0;
      float v01 = acc[mi][nj][1] + b1;
      float v10 = acc[mi][nj][2] + b0;
      float v11 = acc[mi][nj][3] + b1;
      if (EPI == EPI_RELU_BF) {
        v00 = fmaxf(v00, 0.f);
        v01 = fmaxf(v01, 0.f);
        v10 = fmaxf(v10, 0.f);
        v11 = fmaxf(v11, 0.f);
      }
      if (EPI == EPI_RES_F32) {
        float2 r0 = *(const float2*)(res + (size_t)row * Nd + col);
        float2 r1 = *(const float2*)(res + (size_t)(row + 8) * Nd + col);
        v00 += r0.x;
        v01 += r0.y;
        v10 += r1.x;
        v11 += r1.y;
        float2 o0 = {v00, v01}, o1 = {v10, v11};
        *(float2*)(C + (size_t)row * Nd + col) = o0;
        *(float2*)(C + (size_t)(row + 8) * Nd + col) = o1;
      } else {
        *(uint32_t*)(Cb + (size_t)row * Nd + col) = pack_bf16(v00, v01);
        *(uint32_t*)(Cb + (size_t)(row + 8) * Nd + col) = pack_bf16(v10, v11);
      }
    }
  }
}

// ---------------------------------------------------------------------------
// bf16 tensor-core attention (R10, adapted to bf16 in/out).
// ---------------------------------------------------------------------------
constexpr int kQStr = 36;
constexpr int kVStr = 68;
constexpr int kAttnSmem = (2 * 128 * kQStr + 64 * kVStr) * 4;  // 54272

__global__ __launch_bounds__(256, 2) void attn_tc(
    const __nv_bfloat16* __restrict__ qkv, __nv_bfloat16* __restrict__ out) {
  extern __shared__ uint32_t sm[];
  uint32_t* Qs = sm;
  uint32_t* Ks = sm + 128 * kQStr;
  uint32_t* Vt = sm + 2 * 128 * kQStr;
  int t = blockIdx.x >> 2, h = blockIdx.x & 3;
  int tid = threadIdx.x, lane = tid & 31, warp = tid >> 5;
  int g = lane >> 2, tg = lane & 3;
  const size_t base = (size_t)t * kN * (3 * kH);

  // ---- load Q, K, V^T (already bf16) ----
  {
    int row = tid >> 1, part = tid & 1;
    const uint32_t* qp =
        (const uint32_t*)(qkv + base + (size_t)row * (3 * kH) + h * kDH) +
        part * 16;
    const uint32_t* kp = qp + kH / 2;
    uint32_t* qd = Qs + row * kQStr + part * 16;
    uint32_t* kd = Ks + row * kQStr + part * 16;
#pragma unroll
    for (int i = 0; i < 4; ++i) {
      ((uint4*)qd)[i] = ((const uint4*)qp)[i];
      ((uint4*)kd)[i] = ((const uint4*)kp)[i];
    }
    const uint4* vp = (const uint4*)(qkv + base + (size_t)row * (3 * kH) +
                                     2 * kH + h * kDH + part * 32);
    __nv_bfloat16* vtb = (__nv_bfloat16*)Vt;
#pragma unroll
    for (int j = 0; j < 4; ++j) {
      uint4 v = vp[j];
      int d = part * 32 + j * 8;
      __nv_bfloat162 p0 = *(__nv_bfloat162*)&v.x;
      __nv_bfloat162 p1 = *(__nv_bfloat162*)&v.y;
      __nv_bfloat162 p2 = *(__nv_bfloat162*)&v.z;
      __nv_bfloat162 p3 = *(__nv_bfloat162*)&v.w;
      vtb[(d + 0) * (2 * kVStr) + row] = p0.x;
      vtb[(d + 1) * (2 * kVStr) + row] = p0.y;
      vtb[(d + 2) * (2 * kVStr) + row] = p1.x;
      vtb[(d + 3) * (2 * kVStr) + row] = p1.y;
      vtb[(d + 4) * (2 * kVStr) + row] = p2.x;
      vtb[(d + 5) * (2 * kVStr) + row] = p2.y;
      vtb[(d + 6) * (2 * kVStr) + row] = p3.x;
      vtb[(d + 7) * (2 * kVStr) + row] = p3.y;
    }
  }
  __syncthreads();

  // ---- S = Q @ K^T ----
  float sacc[16][4];
#pragma unroll
  for (int nj = 0; nj < 16; ++nj)
#pragma unroll
    for (int c = 0; c < 4; ++c) sacc[nj][c] = 0.f;

  uint32_t a_base = (uint32_t)__cvta_generic_to_shared(
      Qs + (warp * 16 + (lane & 7) + ((lane >> 3) & 1) * 8) * kQStr +
      (lane >> 4) * 4);
  uint32_t k_base = (uint32_t)__cvta_generic_to_shared(
      Ks + ((lane & 7) + (lane >> 4) * 8) * kQStr + ((lane >> 3) & 1) * 4);

#pragma unroll
  for (int ks = 0; ks < 4; ++ks) {
    int kb = ks * 8;
    uint32_t af[4], bf[16][2];
    ldmatrix_x4(af[0], af[1], af[2], af[3], a_base + (uint32_t)(kb * 4));
#pragma unroll
    for (int p = 0; p < 8; ++p) {
      ldmatrix_x4(bf[p * 2][0], bf[p * 2][1], bf[p * 2 + 1][0],
                  bf[p * 2 + 1][1],
                  k_base + (uint32_t)((p * 16 * kQStr + kb) * 4));
    }
#pragma unroll
    for (int nj = 0; nj < 16; ++nj) mma_bf16(sacc[nj], af, bf[nj]);
  }

  // ---- softmax (quad shuffles) ----
  const float scale = 0.125f;
  float mx0 = -1e30f, mx1 = -1e30f;
#pragma unroll
  for (int nj = 0; nj < 16; ++nj) {
    mx0 = fmaxf(mx0, fmaxf(sacc[nj][0], sacc[nj][1]));
    mx1 = fmaxf(mx1, fmaxf(sacc[nj][2], sacc[nj][3]));
  }
  mx0 = fmaxf(mx0, __shfl_xor_sync(~0u, mx0, 1));
  mx0 = fmaxf(mx0, __shfl_xor_sync(~0u, mx0, 2));
  mx1 = fmaxf(mx1, __shfl_xor_sync(~0u, mx1, 1));
  mx1 = fmaxf(mx1, __shfl_xor_sync(~0u, mx1, 2));
  mx0 *= scale;
  mx1 *= scale;
  float sum0 = 0.f, sum1 = 0.f;
#pragma unroll
  for (int nj = 0; nj < 16; ++nj) {
    sacc[nj][0] = __expf(sacc[nj][0] * scale - mx0);
    sacc[nj][1] = __expf(sacc[nj][1] * scale - mx0);
    sacc[nj][2] = __expf(sacc[nj][2] * scale - mx1);
    sacc[nj][3] = __expf(sacc[nj][3] * scale - mx1);
    sum0 += sacc[nj][0] + sacc[nj][1];
    sum1 += sacc[nj][2] + sacc[nj][3];
  }
  sum0 += __shfl_xor_sync(~0u, sum0, 1);
  sum0 += __shfl_xor_sync(~0u, sum0, 2);
  sum1 += __shfl_xor_sync(~0u, sum1, 1);
  sum1 += __shfl_xor_sync(~0u, sum1, 2);
  float inv0 = 1.f / sum0, inv1 = 1.f / sum1;

  uint32_t pfrag[8][4];
#pragma unroll
  for (int ks = 0; ks < 8; ++ks) {
    pfrag[ks][0] = pack_bf16(sacc[2 * ks][0] * inv0, sacc[2 * ks][1] * inv0);
    pfrag[ks][1] = pack_bf16(sacc[2 * ks][2] * inv1, sacc[2 * ks][3] * inv1);
    pfrag[ks][2] =
        pack_bf16(sacc[2 * ks + 1][0] * inv0, sacc[2 * ks + 1][1] * inv0);
    pfrag[ks][3] =
        pack_bf16(sacc[2 * ks + 1][2] * inv1, sacc[2 * ks + 1][3] * inv1);
  }

  // ---- O = P @ V ----
  float oacc[8][4];
#pragma unroll
  for (int nj = 0; nj < 8; ++nj)
#pragma unroll
    for (int c = 0; c < 4; ++c) oacc[nj][c] = 0.f;

  uint32_t v_base = (uint32_t)__cvta_generic_to_shared(
      Vt + ((lane & 7) + (lane >> 4) * 8) * kVStr + ((lane >> 3) & 1) * 4);
#pragma unroll
  for (int ks = 0; ks < 8; ++ks) {
    int kb = ks * 8;
    uint32_t bf[8][2];
#pragma unroll
    for (int p = 0; p < 4; ++p) {
      ldmatrix_x4(bf[p * 2][0], bf[p * 2][1], bf[p * 2 + 1][0],
                  bf[p * 2 + 1][1],
                  v_base + (uint32_t)((p * 16 * kVStr + kb) * 4));
    }
#pragma unroll
    for (int nj = 0; nj < 8; ++nj) mma_bf16(oacc[nj], pfrag[ks], bf[nj]);
  }

  // ---- store O (bf16) ----
  int r0 = warp * 16 + g, r1 = r0 + 8;
  __nv_bfloat16* op = out + (size_t)(t * kN) * kH + h * kDH;
#pragma unroll
  for (int nj = 0; nj < 8; ++nj) {
    int col = nj * 8 + tg * 2;
    *(uint32_t*)(op + (size_t)r0 * kH + col) =
        pack_bf16(oacc[nj][0], oacc[nj][1]);
    *(uint32_t*)(op + (size_t)r1 * kH + col) =
        pack_bf16(oacc[nj][2], oacc[nj][3]);
  }
}

// ---------------------------------------------------------------------------
// LayerNorm: warp per token; writes fp32 x and bf16 xb.
// ---------------------------------------------------------------------------
__global__ __launch_bounds__(256) void ln_kernel(
    const float* __restrict__ y, const float* __restrict__ w,
    const float* __restrict__ b, float* __restrict__ x,
    __nv_bfloat16* __restrict__ xb) {
  int warp = threadIdx.x >> 5, lane = threadIdx.x & 31;
  size_t tok = (size_t)blockIdx.x * 8 + warp;
  const float* yp = y + tok * kH;
  float4 a = *(const float4*)(yp + lane * 4);
  float4 c = *(const float4*)(yp + 128 + lane * 4);
  float sum = a.x + a.y + a.z + a.w + c.x + c.y + c.z + c.w;
#pragma unroll
  for (int s = 16; s; s >>= 1) sum += __shfl_xor_sync(~0u, sum, s);
  float mu = sum * (1.f / kH);
  float d0 = a.x - mu, d1 = a.y - mu, d2 = a.z - mu, d3 = a.w - mu;
  float d4 = c.x - mu, d5 = c.y - mu, d6 = c.z - mu, d7 = c.w - mu;
  float sq = d0 * d0 + d1 * d1 + d2 * d2 + d3 * d3 + d4 * d4 + d5 * d5 +
             d6 * d6 + d7 * d7;
#pragma unroll
  for (int s = 16; s; s >>= 1) sq += __shfl_xor_sync(~0u, sq, s);
  float inv = rsqrtf(sq * (1.f / kH) + 1e-5f);
  float4 w0 = *(const float4*)(w + lane * 4);
  float4 w1 = *(const float4*)(w + 128 + lane * 4);
  float4 b0 = *(const float4*)(b + lane * 4);
  float4 b1 = *(const float4*)(b + 128 + lane * 4);
  float* xp = x + tok * kH;
  float4 o0 = {d0 * inv * w0.x + b0.x, d1 * inv * w0.y + b0.y,
               d2 * inv * w0.z + b0.z, d3 * inv * w0.w + b0.w};
  float4 o1 = {d4 * inv * w1.x + b1.x, d5 * inv * w1.y + b1.y,
               d6 * inv * w1.z + b1.z, d7 * inv * w1.w + b1.w};
  *(float4*)(xp + lane * 4) = o0;
  *(float4*)(xp + 128 + lane * 4) = o1;
  uint2 p0 = {pack_bf16(o0.x, o0.y), pack_bf16(o0.z, o0.w)};
  uint2 p1 = {pack_bf16(o1.x, o1.y), pack_bf16(o1.z, o1.w)};
  *(uint2*)(xb + tok * kH + lane * 4) = p0;
  *(uint2*)(xb + tok * kH + 128 + lane * 4) = p1;
}

// ---------------------------------------------------------------------------
// Output GEMM: out_pre[512,64] = x[512, 32768] @ W_out[64,32768]^T, split-K
// ---------------------------------------------------------------------------
constexpr int kKTotal = kN * kH;
constexpr int kKSplit = 16;
constexpr int kKChunk = kKTotal / kKSplit;

__global__ void zero_outpre() {
  int i = blockIdx.x * blockDim.x + threadIdx.x;
  if (i < kT * kOut) g_outpre[i] = 0.f;
}

__global__ void gemm_out_kernel(const float* __restrict__ Afull,
                                const float* __restrict__ Wout) {
  __shared__ float As[16][68];
  __shared__ float Bs[16][68];
  int m0 = blockIdx.y * 64;
  int kc0 = blockIdx.x * kKChunk;
  int tid = threadIdx.x;
  int tx = tid & 15, ty = tid >> 4;
  int lm = tid >> 2, lk = (tid & 3) * 4;
  float acc[4][4] = {};
  const float* Aptr = Afull + (size_t)(m0 + lm) * kKTotal + kc0 + lk;
  const float* Wptr = Wout + (size_t)lm * kKTotal + kc0 + lk;
  for (int k0 = 0; k0 < kKChunk; k0 += 16) {
    float4 av = *(const float4*)(Aptr + k0);
    float4 wv = *(const float4*)(Wptr + k0);
    As[lk + 0][lm] = av.x;
    As[lk + 1][lm] = av.y;
    As[lk + 2][lm] = av.z;
    As[lk + 3][lm] = av.w;
    Bs[lk + 0][lm] = wv.x;
    Bs[lk + 1][lm] = wv.y;
    Bs[lk + 2][lm] = wv.z;
    Bs[lk + 3][lm] = wv.w;
    __syncthreads();
#pragma unroll
    for (int k = 0; k < 16; ++k) {
      float4 a4 = *(const float4*)&As[k][ty * 4];
      float4 b4 = *(const float4*)&Bs[k][tx * 4];
      float a[4] = {a4.x, a4.y, a4.z, a4.w};
      float b[4] = {b4.x, b4.y, b4.z, b4.w};
#pragma unroll
      for (int i = 0; i < 4; ++i)
#pragma unroll
        for (int j = 0; j < 4; ++j) acc[i][j] += a[i] * b[j];
    }
    __syncthreads();
  }
#pragma unroll
  for (int i = 0; i < 4; ++i)
#pragma unroll
    for (int j = 0; j < 4; ++j)
      atomicAdd(&g_outpre[(m0 + ty * 4 + i) * kOut + tx * 4 + j], acc[i][j]);
}

__global__ void lnf_kernel(const float* __restrict__ b_out,
                           const float* __restrict__ w,
                           const float* __restrict__ bb,
                           float* __restrict__ out) {
  __shared__ float red[64];
  int t = blockIdx.x, o = threadIdx.x;
  float v = g_outpre[t * kOut + o] + b_out[o];
  red[o] = v;
  __syncthreads();
  for (int s = 32; s > 0; s >>= 1) {
    if (o < s) red[o] += red[o + s];
    __syncthreads();
  }
  float mu = red[0] * (1.f / kOut);
  __syncthreads();
  float d = v - mu;
  red[o] = d * d;
  __syncthreads();
  for (int s = 32; s > 0; s >>= 1) {
    if (o < s) red[o] += red[o + s];
    __syncthreads();
  }
  float var = red[0] * (1.f / kOut);
  out[t * kOut + o] = d * rsqrtf(var + 1e-5f) * w[o] + bb[o];
}

}  // namespace

extern "C" void kernel_launch(void* const* d_in, const int* in_sizes, int n_in,
                              void* d_out, int out_size) {
  const float* forest = (const float*)d_in[0];
  const int* adj = (const int*)d_in[1];
  const int* no = (const int*)d_in[2];
  const float* W_in = (const float*)d_in[3];
  const float* b_in = (const float*)d_in[4];
  const float* W_pos = (const float*)d_in[5];
  const float* b_pos = (const float*)d_in[6];
  const float* qkv_w = (const float*)d_in[7];
  const float* qkv_b = (const float*)d_in[8];
  const float* outp_w = (const float*)d_in[9];
  const float* outp_b = (const float*)d_in[10];
  const float* ln1_w = (const float*)d_in[11];
  const float* ln1_b = (const float*)d_in[12];
  const float* ff1_w = (const float*)d_in[13];
  const float* ff1_b = (const float*)d_in[14];
  const float* ff2_w = (const float*)d_in[15];
  const float* ff2_b = (const float*)d_in[16];
  const float* ln2_w = (const float*)d_in[17];
  const float* ln2_b = (const float*)d_in[18];
  const float* W_out = (const float*)d_in[19];
  const float* b_out = (const float*)d_in[20];
  const float* lnf_w = (const float*)d_in[21];
  const float* lnf_b = (const float*)d_in[22];
  float* out = (float*)d_out;

  float *px, *py;
  __nv_bfloat16 *pxb, *pqkvb, *pattnb, *pffb, *pwbf;
  cudaGetSymbolAddress((void**)&px, g_x);
  cudaGetSymbolAddress((void**)&py, g_y);
  cudaGetSymbolAddress((void**)&pxb, g_xb);
  cudaGetSymbolAddress((void**)&pqkvb, g_qkvb);
  cudaGetSymbolAddress((void**)&pattnb, g_attnb);
  cudaGetSymbolAddress((void**)&pffb, g_ffb);
  cudaGetSymbolAddress((void**)&pwbf, g_wbf);

  cudaFuncSetAttribute(attn_tc, cudaFuncAttributeMaxDynamicSharedMemorySize,
                       kAttnSmem);

  // launch 0
  prep_parent_kernel<<<(kTN + 255) / 256, 256>>>(adj);
  // launch 1 (maxno + wpos transpose + weight bf16 conversion)
  prep2_kernel<<<kT + 384 + kWTotal / 256, 256>>>(no, W_pos, qkv_w, outp_w,
                                                  ff1_w, ff2_w);
  // launch 2
  embed_kernel<<<kTN / 32, 256>>>(forest, no, W_in, b_in, b_pos);

  dim3 blk(256);
  for (int l = 0; l < kL; ++l) {
    // launch 3 on l==0: ncu profiles this (qkv GEMM).
    gemm_bf<EPI_QKV_BF><<<dim3((3 * kH) / 128, kTN / 128), blk>>>(
        pxb, pwbf + kWOffQkv + (size_t)l * 3 * kH * kH,
        qkv_b + (size_t)l * 3 * kH, nullptr, nullptr, pqkvb, kTN, 3 * kH, kH);
    attn_tc<<<kT * kHeads, 256, kAttnSmem>>>(pqkvb, pattnb);
    gemm_bf<EPI_RES_F32><<<dim3(kH / 128, kTN / 128), blk>>>(
        pattnb, pwbf + kWOffOutp + (size_t)l * kH * kH,
        outp_b + (size_t)l * kH, px, py, nullptr, kTN, kH, kH);
    ln_kernel<<<kTN / 8, 256>>>(py, ln1_w + (size_t)l * kH,
                                ln1_b + (size_t)l * kH, px, pxb);
    gemm_bf<EPI_RELU_BF><<<dim3(kFF / 128, kTN / 128), blk>>>(
        pxb, pwbf + kWOffFf1 + (size_t)l * kFF * kH, ff1_b + (size_t)l * kFF,
        nullptr, nullptr, pffb, kTN, kFF, kH);
    gemm_bf<EPI_RES_F32><<<dim3(kH / 128, kTN / 128), blk>>>(
        pffb, pwbf + kWOffFf2 + (size_t)l * kH * kFF, ff2_b + (size_t)l * kH,
        px, py, nullptr, kTN, kH, kFF);
    ln_kernel<<<kTN / 8, 256>>>(py, ln2_w + (size_t)l * kH,
                                ln2_b + (size_t)l * kH, px, pxb);
  }

  zero_outpre<<<(kT * kOut + 255) / 256, 256>>>();
  gemm_out_kernel<<<dim3(kKSplit, kT / 64), blk>>>(px, W_out);
  lnf_kernel<<<kT, kOut>>>(b_out, lnf_w, lnf_b, out);
}